// round 11
// baseline (speedup 1.0000x reference)
#include <cuda_runtime.h>
#include <cuda_bf16.h>
#include <cstdint>
#include <math.h>

#define D_DIM 1024
#define I_DIM 4096
#define E_NUM 8
#define TOPK  2
#define T_MAX 2048
#define PADR  128
#define NPOS  (T_MAX*TOPK + E_NUM*PADR)   // 5120
#define NROWTILE (NPOS/PADR)              // 40

// ---- GEMM1 stage: A(x) 128r hi/lo + B1 64r hi/lo + B3 64r hi/lo, 80B pitch --
#define STAGE1 40960
#define O1_AH  0
#define O1_AL  10240
#define O1_B1H 20480
#define O1_B1L 25600
#define O1_B3H 30720
#define O1_B3L 35840
#define SMEM1  (512 + 2*STAGE1)           // 82432, 2 CTAs/SM

// ---- GEMM2 stage: A(h) 128r hi/lo + B(w2) 64r hi/lo ------------------------
#define STAGE2 30720
#define O2_AH  0
#define O2_AL  10240
#define O2_BH  20480
#define O2_BL  25600
#define SMEM2  (3*STAGE2)                 // 92160, 2 CTAs/SM

// ---------------- scratch ----------------------------------------------------
__device__ int   g_counts[E_NUM];
__device__ int   g_offsets[E_NUM + 1];
__device__ int   g_cursor[E_NUM];
__device__ int   g_tile_expert[NROWTILE];
__device__ int   g_pos_token[NPOS];
__device__ float g_pos_wt[NPOS];
__device__ int   g_slot_pos[T_MAX * TOPK];
__device__ int   g_tok_eidx[T_MAX * TOPK];
__device__ float g_tok_ewt[T_MAX * TOPK];

__device__ __nv_bfloat16 g_xh[(size_t)T_MAX * D_DIM];
__device__ __nv_bfloat16 g_xl[(size_t)T_MAX * D_DIM];
__device__ __nv_bfloat16 g_w1h[(size_t)E_NUM * I_DIM * D_DIM];
__device__ __nv_bfloat16 g_w1l[(size_t)E_NUM * I_DIM * D_DIM];
__device__ __nv_bfloat16 g_w3h[(size_t)E_NUM * I_DIM * D_DIM];
__device__ __nv_bfloat16 g_w3l[(size_t)E_NUM * I_DIM * D_DIM];
__device__ __nv_bfloat16 g_w2h[(size_t)E_NUM * D_DIM * I_DIM];
__device__ __nv_bfloat16 g_w2l[(size_t)E_NUM * D_DIM * I_DIM];
__device__ __nv_bfloat16 g_hh[(size_t)NPOS * I_DIM];
__device__ __nv_bfloat16 g_hl[(size_t)NPOS * I_DIM];
__device__ float g_y[(size_t)NPOS * D_DIM];
__device__ float g_y2[(size_t)NPOS * D_DIM];

// ---------------- helpers ----------------------------------------------------
__device__ __forceinline__ uint32_t smem_u32(const void* p) {
    uint32_t a;
    asm("{ .reg .u64 t; cvta.to.shared.u64 t, %1; cvt.u32.u64 %0, t; }" : "=r"(a) : "l"(p));
    return a;
}
__device__ __forceinline__ void ldm_x4(uint32_t* r, uint32_t addr) {
    asm volatile("ldmatrix.sync.aligned.m8n8.x4.shared.b16 {%0,%1,%2,%3}, [%4];"
        : "=r"(r[0]), "=r"(r[1]), "=r"(r[2]), "=r"(r[3]) : "r"(addr));
}
__device__ __forceinline__ void mma_bf16(float* c, const uint32_t* a, uint32_t b0, uint32_t b1) {
    asm volatile("mma.sync.aligned.m16n8k16.row.col.f32.bf16.bf16.f32 "
        "{%0,%1,%2,%3}, {%4,%5,%6,%7}, {%8,%9}, {%0,%1,%2,%3};"
        : "+f"(c[0]), "+f"(c[1]), "+f"(c[2]), "+f"(c[3])
        : "r"(a[0]), "r"(a[1]), "r"(a[2]), "r"(a[3]), "r"(b0), "r"(b1));
}
__device__ __forceinline__ void cp16(uint32_t dst, const void* src) {
    asm volatile("cp.async.cg.shared.global [%0], [%1], 16;" :: "r"(dst), "l"(src) : "memory");
}
__device__ __forceinline__ void cp16z(uint32_t dst, const void* src, int nbytes) {
    asm volatile("cp.async.cg.shared.global [%0], [%1], 16, %2;"
        :: "r"(dst), "l"(src), "r"(nbytes) : "memory");
}
__device__ __forceinline__ void cp_commit() {
    asm volatile("cp.async.commit_group;" ::: "memory");
}
template <int N>
__device__ __forceinline__ void cp_wait() {
    asm volatile("cp.async.wait_group %0;" :: "n"(N) : "memory");
}
__device__ __forceinline__ void split2(float a, float b, uint32_t& h, uint32_t& l) {
    __nv_bfloat162 hh = __floats2bfloat162_rn(a, b);
    __nv_bfloat162 ll = __floats2bfloat162_rn(a - __bfloat162float(hh.x),
                                              b - __bfloat162float(hh.y));
    h = reinterpret_cast<uint32_t&>(hh);
    l = reinterpret_cast<uint32_t&>(ll);
}

// ---------------- small kernels ----------------------------------------------
__global__ void init_kernel() {
    int i = blockIdx.x * blockDim.x + threadIdx.x;
    if (i < E_NUM) g_counts[i] = 0;
    if (i < NPOS) { g_pos_token[i] = -1; g_pos_wt[i] = 0.f; }
}

// fused split of w1, w3, w2 (equal sizes) in one launch
__global__ void split_w_kernel(const float* __restrict__ w1,
                               const float* __restrict__ w3,
                               const float* __restrict__ w2,
                               __nv_bfloat16* __restrict__ w1h, __nv_bfloat16* __restrict__ w1l,
                               __nv_bfloat16* __restrict__ w3h, __nv_bfloat16* __restrict__ w3l,
                               __nv_bfloat16* __restrict__ w2h, __nv_bfloat16* __restrict__ w2l,
                               int n4) {
    int i = blockIdx.x * blockDim.x + threadIdx.x;
    if (i >= 3 * n4) return;
    const float* src; __nv_bfloat16* hi; __nv_bfloat16* lo;
    int j = i;
    if (i < n4)          { src = w1; hi = w1h; lo = w1l; }
    else if (i < 2 * n4) { src = w3; hi = w3h; lo = w3l; j = i - n4; }
    else                 { src = w2; hi = w2h; lo = w2l; j = i - 2 * n4; }
    float4 v = ((const float4*)src)[j];
    uint32_t h0, l0, h1, l1;
    split2(v.x, v.y, h0, l0);
    split2(v.z, v.w, h1, l1);
    ((uint2*)hi)[j] = make_uint2(h0, h1);
    ((uint2*)lo)[j] = make_uint2(l0, l1);
}

__global__ void split_kernel(const float* __restrict__ src,
                             __nv_bfloat16* __restrict__ hi,
                             __nv_bfloat16* __restrict__ lo, int n4) {
    int i = blockIdx.x * blockDim.x + threadIdx.x;
    if (i >= n4) return;
    float4 v = ((const float4*)src)[i];
    uint32_t h0, l0, h1, l1;
    split2(v.x, v.y, h0, l0);
    split2(v.z, v.w, h1, l1);
    ((uint2*)hi)[i] = make_uint2(h0, h1);
    ((uint2*)lo)[i] = make_uint2(l0, l1);
}

__global__ void gate_kernel(const float* __restrict__ x,
                            const float* __restrict__ gw, int T) {
    int gtid = blockIdx.x * blockDim.x + threadIdx.x;
    int warp = gtid >> 5, lane = gtid & 31;
    if (warp >= T) return;
    const float* xr = x + (size_t)warp * D_DIM;
    float acc[E_NUM];
#pragma unroll
    for (int e = 0; e < E_NUM; e++) acc[e] = 0.f;
    for (int k = lane; k < D_DIM; k += 32) {
        float xv = xr[k];
#pragma unroll
        for (int e = 0; e < E_NUM; e++)
            acc[e] = fmaf(xv, gw[e * D_DIM + k], acc[e]);
    }
#pragma unroll
    for (int e = 0; e < E_NUM; e++)
#pragma unroll
        for (int off = 16; off > 0; off >>= 1)
            acc[e] += __shfl_down_sync(0xFFFFFFFFu, acc[e], off);
    if (lane == 0) {
        int i0 = 0;
#pragma unroll
        for (int e = 1; e < E_NUM; e++) if (acc[e] > acc[i0]) i0 = e;
        int i1 = (i0 == 0) ? 1 : 0;
#pragma unroll
        for (int e = 0; e < E_NUM; e++)
            if (e != i0 && acc[e] > acc[i1]) i1 = e;
        float m = fmaxf(acc[i0], acc[i1]);
        float p0 = __expf(acc[i0] - m), p1 = __expf(acc[i1] - m);
        float s = p0 + p1;
        int base = warp * TOPK;
        g_tok_eidx[base + 0] = i0; g_tok_ewt[base + 0] = p0 / s;
        g_tok_eidx[base + 1] = i1; g_tok_ewt[base + 1] = p1 / s;
        atomicAdd(&g_counts[i0], 1);
        atomicAdd(&g_counts[i1], 1);
    }
}

__global__ void offsets_kernel() {
    if (threadIdx.x == 0 && blockIdx.x == 0) {
        int total = 0;
        for (int e = 0; e < E_NUM; e++) {
            g_offsets[e] = total;
            g_cursor[e]  = total;
            total += (g_counts[e] + PADR - 1) & ~(PADR - 1);
        }
        g_offsets[E_NUM] = total;
        for (int t = 0; t < NROWTILE; t++) {
            int r0 = t * PADR;
            int e = 0;
            while (e < E_NUM - 1 && r0 >= g_offsets[e + 1]) e++;
            g_tile_expert[t] = (r0 < total) ? e : -1;
        }
    }
}

__global__ void scatter_kernel(int T) {
    int idx = blockIdx.x * blockDim.x + threadIdx.x;
    if (idx >= T * TOPK) return;
    int e = g_tok_eidx[idx];
    int pos = atomicAdd(&g_cursor[e], 1);
    g_pos_token[pos] = idx >> 1;
    g_pos_wt[pos]    = g_tok_ewt[idx];
    g_slot_pos[idx]  = pos;
}

// ---------------- GEMM1: CTA 128x64, 8 warps, warp m32xn32 computes D1 AND D3
__global__ __launch_bounds__(256, 2)
void gemm1_kernel() {
    extern __shared__ __align__(128) char sm[];
    int e = g_tile_expert[blockIdx.y];
    if (e < 0) return;
    int tid = threadIdx.x, lane = tid & 31, wid = tid >> 5;
    int r0 = blockIdx.y * PADR, c0 = blockIdx.x * 64;
    int* s_tok = (int*)sm;
    uint32_t tiles_u = smem_u32(sm) + 512;

    if (tid < 128) s_tok[tid] = g_pos_token[r0 + tid];
    __syncthreads();

    int mrow = (wid >> 1) * 32;   // 0,32,64,96
    int ncol = (wid & 1) * 32;    // 0,32

    float c1[2][4][4], c3[2][4][4];
#pragma unroll
    for (int a = 0; a < 2; a++)
#pragma unroll
        for (int b = 0; b < 4; b++)
#pragma unroll
            for (int q = 0; q < 4; q++) { c1[a][b][q] = 0.f; c3[a][b][q] = 0.f; }

    auto issue_stage = [&](int kc, int st) {
        uint32_t base = tiles_u + st * STAGE1;
        int kb = kc * 32;   // bf16 offset
#pragma unroll
        for (int it = 0; it < 8; it++) {
            int gid = it * 256 + tid;
            if (gid < 1024) {
                int hl = gid >> 9, r = (gid >> 2) & 127, cc = gid & 3;
                int tok = s_tok[r];
                const __nv_bfloat16* bp = hl ? g_xl : g_xh;
                const __nv_bfloat16* sp = bp
                    + ((size_t)(tok >= 0 ? tok : 0) * D_DIM + kb + cc * 8);
                cp16z(base + (hl ? O1_AL : O1_AH) + r * 80 + cc * 16, sp,
                      tok >= 0 ? 16 : 0);
            } else {
                int g2 = gid - 1024;
                int is3 = g2 >> 9;
                int g3 = g2 & 511;
                int hl = g3 >> 8, r = (g3 >> 2) & 63, cc = g3 & 3;
                const __nv_bfloat16* wp = is3 ? (hl ? g_w3l : g_w3h)
                                              : (hl ? g_w1l : g_w1h);
                const __nv_bfloat16* sp = wp
                    + (((size_t)e * I_DIM + c0 + r) * D_DIM + kb + cc * 8);
                uint32_t off = (is3 ? O1_B3H : O1_B1H) + (hl ? 5120u : 0u)
                             + r * 80 + cc * 16;
                cp16(base + off, sp);
            }
        }
    };

    auto compute = [&](int st) {
        uint32_t su = tiles_u + st * STAGE1;
#pragma unroll
        for (int kk = 0; kk < 2; kk++) {
            int ko = kk * 32;
            uint32_t ah[2][4], al[2][4];
#pragma unroll
            for (int mt = 0; mt < 2; mt++) {
                uint32_t aaddr = su
                    + (uint32_t)((mrow + mt * 16 + (lane & 15)) * 80 + ko + (lane >> 4) * 16);
                ldm_x4(ah[mt], aaddr);
                ldm_x4(al[mt], aaddr + 10240);
            }
#pragma unroll
            for (int nt = 0; nt < 2; nt++) {
                uint32_t b1h[4], b1l[4], b3h[4], b3l[4];
                uint32_t baddr = su + O1_B1H
                    + (uint32_t)((ncol + nt * 16 + (lane & 15)) * 80 + ko + (lane >> 4) * 16);
                ldm_x4(b1h, baddr);
                ldm_x4(b1l, baddr + 5120);
                ldm_x4(b3h, baddr + 10240);
                ldm_x4(b3l, baddr + 15360);
#pragma unroll
                for (int mt = 0; mt < 2; mt++)
#pragma unroll
                    for (int sub = 0; sub < 2; sub++) {
                        float* cc1 = c1[mt][nt * 2 + sub];
                        mma_bf16(cc1, ah[mt], b1h[sub], b1h[sub + 2]);
                        mma_bf16(cc1, al[mt], b1h[sub], b1h[sub + 2]);
                        mma_bf16(cc1, ah[mt], b1l[sub], b1l[sub + 2]);
                        float* cc3 = c3[mt][nt * 2 + sub];
                        mma_bf16(cc3, ah[mt], b3h[sub], b3h[sub + 2]);
                        mma_bf16(cc3, al[mt], b3h[sub], b3h[sub + 2]);
                        mma_bf16(cc3, ah[mt], b3l[sub], b3l[sub + 2]);
                    }
            }
        }
    };

    issue_stage(0, 0); cp_commit();
    issue_stage(1, 1); cp_commit();
#pragma unroll 1
    for (int kc = 0; kc < 32; kc++) {
        if (kc < 31) cp_wait<1>(); else cp_wait<0>();
        __syncthreads();
        compute(kc & 1);
        __syncthreads();
        if (kc + 2 < 32) { issue_stage(kc + 2, kc & 1); cp_commit(); }
    }

    // epilogue: both accumulators in-warp — no exchange
#pragma unroll
    for (int mt = 0; mt < 2; mt++)
#pragma unroll
        for (int ns = 0; ns < 4; ns++) {
            int row = mrow + mt * 16 + (lane >> 2);
            int col = c0 + ncol + ns * 8 + 2 * (lane & 3);
            float* a1 = c1[mt][ns];
            float* a3 = c3[mt][ns];
            float v0 = a1[0] * a3[0] / (1.f + __expf(-a1[0]));
            float v1 = a1[1] * a3[1] / (1.f + __expf(-a1[1]));
            float v2 = a1[2] * a3[2] / (1.f + __expf(-a1[2]));
            float v3 = a1[3] * a3[3] / (1.f + __expf(-a1[3]));
            uint32_t ha, la, hb, lb;
            split2(v0, v1, ha, la);
            split2(v2, v3, hb, lb);
            size_t o0 = (size_t)(r0 + row) * I_DIM + col;
            size_t o1 = (size_t)(r0 + row + 8) * I_DIM + col;
            *(uint32_t*)(g_hh + o0) = ha;
            *(uint32_t*)(g_hl + o0) = la;
            *(uint32_t*)(g_hh + o1) = hb;
            *(uint32_t*)(g_hl + o1) = lb;
        }
}

// ---------------- GEMM2: CTA 128x64, split-K x2; y_part = (h·w2ᵀ)*wt ---------
__global__ __launch_bounds__(256, 2)
void gemm2_kernel() {
    extern __shared__ __align__(128) char sm[];
    int e = g_tile_expert[blockIdx.y];
    if (e < 0) return;
    int tid = threadIdx.x, lane = tid & 31, wid = tid >> 5;
    int r0 = blockIdx.y * PADR, c0 = blockIdx.x * 64;
    int ks = blockIdx.z;              // K-split half: chunks [ks*64, ks*64+64)
    int kbase = ks * 64;
    uint32_t tiles_u = smem_u32(sm);

    int mrow = (wid >> 1) * 32;
    int ncol = (wid & 1) * 32;

    float c[2][4][4];
#pragma unroll
    for (int a = 0; a < 2; a++)
#pragma unroll
        for (int b = 0; b < 4; b++)
#pragma unroll
            for (int q = 0; q < 4; q++) c[a][b][q] = 0.f;

    auto issue_stage = [&](int kc, int st) {
        uint32_t base = tiles_u + st * STAGE2;
        int kb = (kbase + kc) * 32;
#pragma unroll
        for (int it = 0; it < 6; it++) {
            int gid = it * 256 + tid;
            if (gid < 1024) {
                int hl = gid >> 9, r = (gid >> 2) & 127, cc = gid & 3;
                const __nv_bfloat16* bp = hl ? g_hl : g_hh;
                const __nv_bfloat16* sp = bp
                    + ((size_t)(r0 + r) * I_DIM + kb + cc * 8);
                cp16(base + (hl ? O2_AL : O2_AH) + r * 80 + cc * 16, sp);
            } else {
                int g2 = gid - 1024;
                int hl = g2 >> 8, r = (g2 >> 2) & 63, cc = g2 & 3;
                const __nv_bfloat16* wp = hl ? g_w2l : g_w2h;
                const __nv_bfloat16* sp = wp
                    + (((size_t)e * D_DIM + c0 + r) * I_DIM + kb + cc * 8);
                cp16(base + (hl ? O2_BL : O2_BH) + r * 80 + cc * 16, sp);
            }
        }
    };

    auto compute = [&](int st) {
        uint32_t su = tiles_u + st * STAGE2;
#pragma unroll
        for (int kk = 0; kk < 2; kk++) {
            int ko = kk * 32;
            uint32_t ah[2][4], al[2][4];
#pragma unroll
            for (int mt = 0; mt < 2; mt++) {
                uint32_t aaddr = su
                    + (uint32_t)((mrow + mt * 16 + (lane & 15)) * 80 + ko + (lane >> 4) * 16);
                ldm_x4(ah[mt], aaddr);
                ldm_x4(al[mt], aaddr + 10240);
            }
#pragma unroll
            for (int nt = 0; nt < 2; nt++) {
                uint32_t bh[4], bl[4];
                uint32_t baddr = su + O2_BH
                    + (uint32_t)((ncol + nt * 16 + (lane & 15)) * 80 + ko + (lane >> 4) * 16);
                ldm_x4(bh, baddr);
                ldm_x4(bl, baddr + 5120);
#pragma unroll
                for (int mt = 0; mt < 2; mt++)
#pragma unroll
                    for (int sub = 0; sub < 2; sub++) {
                        float* cc = c[mt][nt * 2 + sub];
                        mma_bf16(cc, ah[mt], bh[sub], bh[sub + 2]);
                        mma_bf16(cc, al[mt], bh[sub], bh[sub + 2]);
                        mma_bf16(cc, ah[mt], bl[sub], bl[sub + 2]);
                    }
            }
        }
    };

    issue_stage(0, 0); cp_commit();
    issue_stage(1, 1); cp_commit();
#pragma unroll 1
    for (int kc = 0; kc < 64; kc++) {
        if (kc < 63) cp_wait<1>(); else cp_wait<0>();
        __syncthreads();
        if (kc + 2 < 64) { issue_stage(kc + 2, (kc + 2) % 3); cp_commit(); }
        compute(kc % 3);
    }

    float* yout = ks ? g_y2 : g_y;
#pragma unroll
    for (int mt = 0; mt < 2; mt++) {
        int row = mrow + mt * 16 + (lane >> 2);
        float wa = g_pos_wt[r0 + row];
        float wb = g_pos_wt[r0 + row + 8];
#pragma unroll
        for (int ns = 0; ns < 4; ns++) {
            int col = c0 + ncol + ns * 8 + 2 * (lane & 3);
            float* cc = c[mt][ns];
            *(float2*)(yout + (size_t)(r0 + row) * D_DIM + col)
                = make_float2(cc[0] * wa, cc[1] * wa);
            *(float2*)(yout + (size_t)(r0 + row + 8) * D_DIM + col)
                = make_float2(cc[2] * wb, cc[3] * wb);
        }
    }
}

// ---------------- combine: out[t] = (y+y2)[p0] + (y+y2)[p1] ------------------
__global__ void combine_kernel(float* __restrict__ out, int T) {
    int idx = blockIdx.x * blockDim.x + threadIdx.x;
    int total = T * (D_DIM / 4);
    if (idx >= total) return;
    int t = idx / (D_DIM / 4);
    int d4 = idx - t * (D_DIM / 4);
    int p0 = g_slot_pos[2 * t];
    int p1 = g_slot_pos[2 * t + 1];
    const float4* ya0 = (const float4*)(g_y  + (size_t)p0 * D_DIM) + d4;
    const float4* yb0 = (const float4*)(g_y2 + (size_t)p0 * D_DIM) + d4;
    const float4* ya1 = (const float4*)(g_y  + (size_t)p1 * D_DIM) + d4;
    const float4* yb1 = (const float4*)(g_y2 + (size_t)p1 * D_DIM) + d4;
    float4 a = *ya0, b = *yb0, cc = *ya1, d = *yb1;
    float4 r;
    r.x = (a.x + b.x) + (cc.x + d.x);
    r.y = (a.y + b.y) + (cc.y + d.y);
    r.z = (a.z + b.z) + (cc.z + d.z);
    r.w = (a.w + b.w) + (cc.w + d.w);
    ((float4*)out)[idx] = r;
}

// ---------------- launch -----------------------------------------------------
extern "C" void kernel_launch(void* const* d_in, const int* in_sizes, int n_in,
                              void* d_out, int out_size) {
    const float* x  = (const float*)d_in[0];
    const float* gw = (const float*)d_in[1];
    const float* w1 = (const float*)d_in[2];
    const float* w2 = (const float*)d_in[3];
    const float* w3 = (const float*)d_in[4];
    float* out = (float*)d_out;

    int T = in_sizes[0] / D_DIM;
    if (T > T_MAX) T = T_MAX;

    cudaFuncSetAttribute(gemm1_kernel, cudaFuncAttributeMaxDynamicSharedMemorySize, SMEM1);
    cudaFuncSetAttribute(gemm2_kernel, cudaFuncAttributeMaxDynamicSharedMemorySize, SMEM2);

    init_kernel<<<(NPOS + 255) / 256, 256>>>();
    gate_kernel<<<(T * 32 + 255) / 256, 256>>>(x, gw, T);
    offsets_kernel<<<1, 32>>>();
    scatter_kernel<<<(T * TOPK + 255) / 256, 256>>>(T);

    // one-time fp32 -> bf16 hi/lo pre-splits (x + fused weights)
    {
        __nv_bfloat16 *xh, *xl, *w1h, *w1l, *w3h, *w3l, *w2h, *w2l;
        cudaGetSymbolAddress((void**)&xh,  g_xh);
        cudaGetSymbolAddress((void**)&xl,  g_xl);
        cudaGetSymbolAddress((void**)&w1h, g_w1h);
        cudaGetSymbolAddress((void**)&w1l, g_w1l);
        cudaGetSymbolAddress((void**)&w3h, g_w3h);
        cudaGetSymbolAddress((void**)&w3l, g_w3l);
        cudaGetSymbolAddress((void**)&w2h, g_w2h);
        cudaGetSymbolAddress((void**)&w2l, g_w2l);
        int nx4 = T * D_DIM / 4;
        int nw4 = E_NUM * I_DIM * D_DIM / 4;
        split_kernel<<<(nx4 + 255) / 256, 256>>>(x, xh, xl, nx4);
        split_w_kernel<<<(3 * nw4 + 255) / 256, 256>>>(w1, w3, w2,
                                                       w1h, w1l, w3h, w3l,
                                                       w2h, w2l, nw4);
    }

    dim3 grid1(I_DIM / 64, NROWTILE);
    gemm1_kernel<<<grid1, 256, SMEM1>>>();

    dim3 grid2(D_DIM / 64, NROWTILE, 2);
    gemm2_kernel<<<grid2, 256, SMEM2>>>();

    combine_kernel<<<(T * (D_DIM / 4) + 255) / 256, 256>>>(out, T);
}

// round 13
// speedup vs baseline: 1.0388x; 1.0388x over previous
#include <cuda_runtime.h>
#include <cuda_bf16.h>
#include <cstdint>
#include <math.h>

#define D_DIM 1024
#define I_DIM 4096
#define E_NUM 8
#define TOPK  2
#define T_MAX 2048
#define PADG  64                          // expert group padding granularity
#define NPOS  (T_MAX*TOPK + E_NUM*128)    // 5120 (upper bound)
#define NTILE 44                          // max 128-row tiles (<=40 needed)

// ---- GEMM1 stage: A(x) 128r hi/lo + B1 64r hi/lo + B3 64r hi/lo, 80B pitch --
#define STAGE1 40960
#define O1_AH  0
#define O1_AL  10240
#define O1_B1H 20480
#define O1_B1L 25600
#define O1_B3H 30720
#define O1_B3L 35840
#define SMEM1  (512 + 2*STAGE1)           // 82432, 2 CTAs/SM

// ---- GEMM2 stage: A(h) 128r hi/lo + B(w2) 64r hi/lo ------------------------
#define STAGE2 30720
#define O2_AH  0
#define O2_AL  10240
#define O2_BH  20480
#define O2_BL  25600
#define SMEM2  (3*STAGE2)                 // 92160, 2 CTAs/SM

// ---------------- scratch ----------------------------------------------------
__device__ int   g_counts[E_NUM];
__device__ int   g_offsets[E_NUM + 1];
__device__ int   g_cursor[E_NUM];
__device__ int   g_tile_expert[NTILE];
__device__ int   g_tile_r0[NTILE];
__device__ int   g_tile_rows[NTILE];
__device__ int   g_pos_token[NPOS];
__device__ float g_pos_wt[NPOS];
__device__ int   g_slot_pos[T_MAX * TOPK];
__device__ int   g_tok_eidx[T_MAX * TOPK];
__device__ float g_tok_ewt[T_MAX * TOPK];

__device__ __nv_bfloat16 g_xh[(size_t)T_MAX * D_DIM];
__device__ __nv_bfloat16 g_xl[(size_t)T_MAX * D_DIM];
__device__ __nv_bfloat16 g_w1h[(size_t)E_NUM * I_DIM * D_DIM];
__device__ __nv_bfloat16 g_w1l[(size_t)E_NUM * I_DIM * D_DIM];
__device__ __nv_bfloat16 g_w3h[(size_t)E_NUM * I_DIM * D_DIM];
__device__ __nv_bfloat16 g_w3l[(size_t)E_NUM * I_DIM * D_DIM];
__device__ __nv_bfloat16 g_w2h[(size_t)E_NUM * D_DIM * I_DIM];
__device__ __nv_bfloat16 g_w2l[(size_t)E_NUM * D_DIM * I_DIM];
__device__ __nv_bfloat16 g_hh[(size_t)NPOS * I_DIM];
__device__ __nv_bfloat16 g_hl[(size_t)NPOS * I_DIM];
__device__ float g_y[(size_t)NPOS * D_DIM];

// ---------------- helpers ----------------------------------------------------
__device__ __forceinline__ uint32_t smem_u32(const void* p) {
    uint32_t a;
    asm("{ .reg .u64 t; cvta.to.shared.u64 t, %1; cvt.u32.u64 %0, t; }" : "=r"(a) : "l"(p));
    return a;
}
__device__ __forceinline__ void ldm_x4(uint32_t* r, uint32_t addr) {
    asm volatile("ldmatrix.sync.aligned.m8n8.x4.shared.b16 {%0,%1,%2,%3}, [%4];"
        : "=r"(r[0]), "=r"(r[1]), "=r"(r[2]), "=r"(r[3]) : "r"(addr));
}
__device__ __forceinline__ void mma_bf16(float* c, const uint32_t* a, uint32_t b0, uint32_t b1) {
    asm volatile("mma.sync.aligned.m16n8k16.row.col.f32.bf16.bf16.f32 "
        "{%0,%1,%2,%3}, {%4,%5,%6,%7}, {%8,%9}, {%0,%1,%2,%3};"
        : "+f"(c[0]), "+f"(c[1]), "+f"(c[2]), "+f"(c[3])
        : "r"(a[0]), "r"(a[1]), "r"(a[2]), "r"(a[3]), "r"(b0), "r"(b1));
}
__device__ __forceinline__ void cp16(uint32_t dst, const void* src) {
    asm volatile("cp.async.cg.shared.global [%0], [%1], 16;" :: "r"(dst), "l"(src) : "memory");
}
__device__ __forceinline__ void cp16z(uint32_t dst, const void* src, int nbytes) {
    asm volatile("cp.async.cg.shared.global [%0], [%1], 16, %2;"
        :: "r"(dst), "l"(src), "r"(nbytes) : "memory");
}
__device__ __forceinline__ void cp_commit() {
    asm volatile("cp.async.commit_group;" ::: "memory");
}
template <int N>
__device__ __forceinline__ void cp_wait() {
    asm volatile("cp.async.wait_group %0;" :: "n"(N) : "memory");
}
__device__ __forceinline__ void split2(float a, float b, uint32_t& h, uint32_t& l) {
    __nv_bfloat162 hh = __floats2bfloat162_rn(a, b);
    __nv_bfloat162 ll = __floats2bfloat162_rn(a - __bfloat162float(hh.x),
                                              b - __bfloat162float(hh.y));
    h = reinterpret_cast<uint32_t&>(hh);
    l = reinterpret_cast<uint32_t&>(ll);
}

// ---------------- init (counts + pos arrays; must precede prep's gate) -------
__global__ void init_kernel() {
    int i = blockIdx.x * blockDim.x + threadIdx.x;
    if (i < E_NUM) g_counts[i] = 0;
    if (i < NPOS) { g_pos_token[i] = -1; g_pos_wt[i] = 0.f; }
}

// ---------------- fused preprocessing: gate + split x + split w1/w3/w2 -------
#define NB_GATE 256      // T_MAX*32/256
#define NB_X    2048     // T_MAX*D_DIM/4/256
#define NB_W    98304    // 3*E*I*D/4/256  (FIXED: was 49152 — covered only half)
__global__ void prep_kernel(const float* __restrict__ x,
                            const float* __restrict__ gw,
                            const float* __restrict__ w1,
                            const float* __restrict__ w3,
                            const float* __restrict__ w2,
                            int T) {
    int b = blockIdx.x;
    int tid = threadIdx.x;
    if (b < NB_GATE) {
        // ---- gate: one warp per token ----
        int gtid = b * 256 + tid;
        int warp = gtid >> 5, lane = gtid & 31;
        if (warp >= T) return;
        const float* xr = x + (size_t)warp * D_DIM;
        float acc[E_NUM];
#pragma unroll
        for (int e = 0; e < E_NUM; e++) acc[e] = 0.f;
        for (int k = lane; k < D_DIM; k += 32) {
            float xv = xr[k];
#pragma unroll
            for (int e = 0; e < E_NUM; e++)
                acc[e] = fmaf(xv, gw[e * D_DIM + k], acc[e]);
        }
#pragma unroll
        for (int e = 0; e < E_NUM; e++)
#pragma unroll
            for (int off = 16; off > 0; off >>= 1)
                acc[e] += __shfl_down_sync(0xFFFFFFFFu, acc[e], off);
        if (lane == 0) {
            int i0 = 0;
#pragma unroll
            for (int e = 1; e < E_NUM; e++) if (acc[e] > acc[i0]) i0 = e;
            int i1 = (i0 == 0) ? 1 : 0;
#pragma unroll
            for (int e = 0; e < E_NUM; e++)
                if (e != i0 && acc[e] > acc[i1]) i1 = e;
            float m = fmaxf(acc[i0], acc[i1]);
            float p0 = __expf(acc[i0] - m), p1 = __expf(acc[i1] - m);
            float s = p0 + p1;
            int base = warp * TOPK;
            g_tok_eidx[base + 0] = i0; g_tok_ewt[base + 0] = p0 / s;
            g_tok_eidx[base + 1] = i1; g_tok_ewt[base + 1] = p1 / s;
            atomicAdd(&g_counts[i0], 1);
            atomicAdd(&g_counts[i1], 1);
        }
    } else if (b < NB_GATE + NB_X) {
        // ---- split x ----
        int i = (b - NB_GATE) * 256 + tid;
        int n4 = T * D_DIM / 4;
        if (i >= n4) return;
        float4 v = ((const float4*)x)[i];
        uint32_t h0, l0, h1, l1;
        split2(v.x, v.y, h0, l0);
        split2(v.z, v.w, h1, l1);
        ((uint2*)g_xh)[i] = make_uint2(h0, h1);
        ((uint2*)g_xl)[i] = make_uint2(l0, l1);
    } else {
        // ---- split w1 / w3 / w2 ----
        int i = (b - NB_GATE - NB_X) * 256 + tid;
        int nw4 = E_NUM * I_DIM * D_DIM / 4;
        if (i >= 3 * nw4) return;
        const float* src; __nv_bfloat16* hi; __nv_bfloat16* lo;
        int j = i;
        if (i < nw4)          { src = w1; hi = g_w1h; lo = g_w1l; }
        else if (i < 2 * nw4) { src = w3; hi = g_w3h; lo = g_w3l; j = i - nw4; }
        else                  { src = w2; hi = g_w2h; lo = g_w2l; j = i - 2 * nw4; }
        float4 v = ((const float4*)src)[j];
        uint32_t h0, l0, h1, l1;
        split2(v.x, v.y, h0, l0);
        split2(v.z, v.w, h1, l1);
        ((uint2*)hi)[j] = make_uint2(h0, h1);
        ((uint2*)lo)[j] = make_uint2(l0, l1);
    }
}

// ---------------- offsets + tile table (64-row group padding) ----------------
__global__ void offsets_kernel() {
    if (threadIdx.x == 0 && blockIdx.x == 0) {
        int total = 0;
        for (int e = 0; e < E_NUM; e++) {
            g_offsets[e] = total;
            g_cursor[e]  = total;
            total += (g_counts[e] + PADG - 1) & ~(PADG - 1);
        }
        g_offsets[E_NUM] = total;
        int nt = 0;
        for (int e = 0; e < E_NUM; e++) {
            int sz = g_offsets[e + 1] - g_offsets[e];
            int r = 0;
            while (r < sz && nt < NTILE) {
                g_tile_expert[nt] = e;
                g_tile_r0[nt]     = g_offsets[e] + r;
                g_tile_rows[nt]   = (sz - r >= 128) ? 128 : 64;
                r += 128;
                nt++;
            }
        }
        for (int t = nt; t < NTILE; t++) g_tile_expert[t] = -1;
    }
}

__global__ void scatter_kernel(int T) {
    int idx = blockIdx.x * blockDim.x + threadIdx.x;
    if (idx >= T * TOPK) return;
    int e = g_tok_eidx[idx];
    int pos = atomicAdd(&g_cursor[e], 1);
    g_pos_token[pos] = idx >> 1;
    g_pos_wt[pos]    = g_tok_ewt[idx];
    g_slot_pos[idx]  = pos;
}

// ---------------- GEMM1: CTA 128x64, 8 warps, warp m32xn32 computes D1 AND D3
__global__ __launch_bounds__(256, 2)
void gemm1_kernel() {
    extern __shared__ __align__(128) char sm[];
    int e = g_tile_expert[blockIdx.y];
    if (e < 0) return;
    int tid = threadIdx.x, lane = tid & 31, wid = tid >> 5;
    int r0 = g_tile_r0[blockIdx.y];
    int rows = g_tile_rows[blockIdx.y];
    int c0 = blockIdx.x * 64;
    int* s_tok = (int*)sm;
    uint32_t tiles_u = smem_u32(sm) + 512;

    if (tid < 128) s_tok[tid] = (tid < rows) ? g_pos_token[r0 + tid] : -1;
    __syncthreads();

    int mrow = (wid >> 1) * 32;   // 0,32,64,96
    int ncol = (wid & 1) * 32;    // 0,32
    bool act = (mrow < rows);

    float c1[2][4][4], c3[2][4][4];
#pragma unroll
    for (int a = 0; a < 2; a++)
#pragma unroll
        for (int b = 0; b < 4; b++)
#pragma unroll
            for (int q = 0; q < 4; q++) { c1[a][b][q] = 0.f; c3[a][b][q] = 0.f; }

    auto issue_stage = [&](int kc, int st) {
        uint32_t base = tiles_u + st * STAGE1;
        int kb = kc * 32;   // bf16 offset
#pragma unroll
        for (int it = 0; it < 8; it++) {
            int gid = it * 256 + tid;
            if (gid < 1024) {
                int hl = gid >> 9, r = (gid >> 2) & 127, cc = gid & 3;
                int tok = s_tok[r];
                const __nv_bfloat16* bp = hl ? g_xl : g_xh;
                const __nv_bfloat16* sp = bp
                    + ((size_t)(tok >= 0 ? tok : 0) * D_DIM + kb + cc * 8);
                cp16z(base + (hl ? O1_AL : O1_AH) + r * 80 + cc * 16, sp,
                      tok >= 0 ? 16 : 0);
            } else {
                int g2 = gid - 1024;
                int is3 = g2 >> 9;
                int g3 = g2 & 511;
                int hl = g3 >> 8, r = (g3 >> 2) & 63, cc = g3 & 3;
                const __nv_bfloat16* wp = is3 ? (hl ? g_w3l : g_w3h)
                                              : (hl ? g_w1l : g_w1h);
                const __nv_bfloat16* sp = wp
                    + (((size_t)e * I_DIM + c0 + r) * D_DIM + kb + cc * 8);
                uint32_t off = (is3 ? O1_B3H : O1_B1H) + (hl ? 5120u : 0u)
                             + r * 80 + cc * 16;
                cp16(base + off, sp);
            }
        }
    };

    auto compute = [&](int st) {
        if (!act) return;   // masked warps: no MMA work (tile has < 128 rows)
        uint32_t su = tiles_u + st * STAGE1;
#pragma unroll
        for (int kk = 0; kk < 2; kk++) {
            int ko = kk * 32;
            uint32_t ah[2][4], al[2][4];
#pragma unroll
            for (int mt = 0; mt < 2; mt++) {
                uint32_t aaddr = su
                    + (uint32_t)((mrow + mt * 16 + (lane & 15)) * 80 + ko + (lane >> 4) * 16);
                ldm_x4(ah[mt], aaddr);
                ldm_x4(al[mt], aaddr + 10240);
            }
#pragma unroll
            for (int nt = 0; nt < 2; nt++) {
                uint32_t b1h[4], b1l[4], b3h[4], b3l[4];
                uint32_t baddr = su + O1_B1H
                    + (uint32_t)((ncol + nt * 16 + (lane & 15)) * 80 + ko + (lane >> 4) * 16);
                ldm_x4(b1h, baddr);
                ldm_x4(b1l, baddr + 5120);
                ldm_x4(b3h, baddr + 10240);
                ldm_x4(b3l, baddr + 15360);
#pragma unroll
                for (int mt = 0; mt < 2; mt++)
#pragma unroll
                    for (int sub = 0; sub < 2; sub++) {
                        float* cc1 = c1[mt][nt * 2 + sub];
                        mma_bf16(cc1, ah[mt], b1h[sub], b1h[sub + 2]);
                        mma_bf16(cc1, al[mt], b1h[sub], b1h[sub + 2]);
                        mma_bf16(cc1, ah[mt], b1l[sub], b1l[sub + 2]);
                        float* cc3 = c3[mt][nt * 2 + sub];
                        mma_bf16(cc3, ah[mt], b3h[sub], b3h[sub + 2]);
                        mma_bf16(cc3, al[mt], b3h[sub], b3h[sub + 2]);
                        mma_bf16(cc3, ah[mt], b3l[sub], b3l[sub + 2]);
                    }
            }
        }
    };

    issue_stage(0, 0); cp_commit();
    issue_stage(1, 1); cp_commit();
#pragma unroll 1
    for (int kc = 0; kc < 32; kc++) {
        if (kc < 31) cp_wait<1>(); else cp_wait<0>();
        __syncthreads();
        compute(kc & 1);
        __syncthreads();
        if (kc + 2 < 32) { issue_stage(kc + 2, kc & 1); cp_commit(); }
    }

    // epilogue: both accumulators in-warp — no exchange
    if (act) {
#pragma unroll
        for (int mt = 0; mt < 2; mt++)
#pragma unroll
            for (int ns = 0; ns < 4; ns++) {
                int row = mrow + mt * 16 + (lane >> 2);
                int col = c0 + ncol + ns * 8 + 2 * (lane & 3);
                float* a1 = c1[mt][ns];
                float* a3 = c3[mt][ns];
                float v0 = a1[0] * a3[0] / (1.f + __expf(-a1[0]));
                float v1 = a1[1] * a3[1] / (1.f + __expf(-a1[1]));
                float v2 = a1[2] * a3[2] / (1.f + __expf(-a1[2]));
                float v3 = a1[3] * a3[3] / (1.f + __expf(-a1[3]));
                uint32_t ha, la, hb, lb;
                split2(v0, v1, ha, la);
                split2(v2, v3, hb, lb);
                size_t o0 = (size_t)(r0 + row) * I_DIM + col;
                size_t o1 = (size_t)(r0 + row + 8) * I_DIM + col;
                *(uint32_t*)(g_hh + o0) = ha;
                *(uint32_t*)(g_hl + o0) = la;
                *(uint32_t*)(g_hh + o1) = hb;
                *(uint32_t*)(g_hl + o1) = lb;
            }
    }
}

// ---------------- GEMM2: CTA 128x64, 8 warps, warp m32xn32; y = (h·w2ᵀ)*wt ---
__global__ __launch_bounds__(256, 2)
void gemm2_kernel() {
    extern __shared__ __align__(128) char sm[];
    int e = g_tile_expert[blockIdx.y];
    if (e < 0) return;
    int tid = threadIdx.x, lane = tid & 31, wid = tid >> 5;
    int r0 = g_tile_r0[blockIdx.y];
    int rows = g_tile_rows[blockIdx.y];
    int c0 = blockIdx.x * 64;
    uint32_t tiles_u = smem_u32(sm);

    int mrow = (wid >> 1) * 32;
    int ncol = (wid & 1) * 32;
    bool act = (mrow < rows);

    float c[2][4][4];
#pragma unroll
    for (int a = 0; a < 2; a++)
#pragma unroll
        for (int b = 0; b < 4; b++)
#pragma unroll
            for (int q = 0; q < 4; q++) c[a][b][q] = 0.f;

    auto issue_stage = [&](int kc, int st) {
        uint32_t base = tiles_u + st * STAGE2;
        int kb = kc * 32;
#pragma unroll
        for (int it = 0; it < 6; it++) {
            int gid = it * 256 + tid;
            if (gid < 1024) {
                int hl = gid >> 9, r = (gid >> 2) & 127, cc = gid & 3;
                // rows >= `rows` in g_hh/g_hl are unwritten garbage, but their
                // MMA outputs land only in masked-out result rows — harmless
                const __nv_bfloat16* bp = hl ? g_hl : g_hh;
                const __nv_bfloat16* sp = bp
                    + ((size_t)(r0 + r) * I_DIM + kb + cc * 8);
                cp16(base + (hl ? O2_AL : O2_AH) + r * 80 + cc * 16, sp);
            } else {
                int g2 = gid - 1024;
                int hl = g2 >> 8, r = (g2 >> 2) & 63, cc = g2 & 3;
                const __nv_bfloat16* wp = hl ? g_w2l : g_w2h;
                const __nv_bfloat16* sp = wp
                    + (((size_t)e * D_DIM + c0 + r) * I_DIM + kb + cc * 8);
                cp16(base + (hl ? O2_BL : O2_BH) + r * 80 + cc * 16, sp);
            }
        }
    };

    auto compute = [&](int st) {
        if (!act) return;
        uint32_t su = tiles_u + st * STAGE2;
#pragma unroll
        for (int kk = 0; kk < 2; kk++) {
            int ko = kk * 32;
            uint32_t ah[2][4], al[2][4];
#pragma unroll
            for (int mt = 0; mt < 2; mt++) {
                uint32_t aaddr = su
                    + (uint32_t)((mrow + mt * 16 + (lane & 15)) * 80 + ko + (lane >> 4) * 16);
                ldm_x4(ah[mt], aaddr);
                ldm_x4(al[mt], aaddr + 10240);
            }
#pragma unroll
            for (int nt = 0; nt < 2; nt++) {
                uint32_t bh[4], bl[4];
                uint32_t baddr = su + O2_BH
                    + (uint32_t)((ncol + nt * 16 + (lane & 15)) * 80 + ko + (lane >> 4) * 16);
                ldm_x4(bh, baddr);
                ldm_x4(bl, baddr + 5120);
#pragma unroll
                for (int mt = 0; mt < 2; mt++)
#pragma unroll
                    for (int sub = 0; sub < 2; sub++) {
                        float* cc = c[mt][nt * 2 + sub];
                        mma_bf16(cc, ah[mt], bh[sub], bh[sub + 2]);
                        mma_bf16(cc, al[mt], bh[sub], bh[sub + 2]);
                        mma_bf16(cc, ah[mt], bl[sub], bl[sub + 2]);
                    }
            }
        }
    };

    issue_stage(0, 0); cp_commit();
    issue_stage(1, 1); cp_commit();
#pragma unroll 1
    for (int kc = 0; kc < 128; kc++) {
        if (kc < 127) cp_wait<1>(); else cp_wait<0>();
        __syncthreads();
        // buffer (kc+2)%3 held stage kc-1; all warps passed the sync after
        // computing it, so overwriting now is race-free (single sync/iter)
        if (kc + 2 < 128) { issue_stage(kc + 2, (kc + 2) % 3); cp_commit(); }
        compute(kc % 3);
    }

    if (act) {
#pragma unroll
        for (int mt = 0; mt < 2; mt++) {
            int row = mrow + mt * 16 + (lane >> 2);
            float wa = g_pos_wt[r0 + row];
            float wb = g_pos_wt[r0 + row + 8];
#pragma unroll
            for (int ns = 0; ns < 4; ns++) {
                int col = c0 + ncol + ns * 8 + 2 * (lane & 3);
                float* cc = c[mt][ns];
                *(float2*)(g_y + (size_t)(r0 + row) * D_DIM + col)
                    = make_float2(cc[0] * wa, cc[1] * wa);
                *(float2*)(g_y + (size_t)(r0 + row + 8) * D_DIM + col)
                    = make_float2(cc[2] * wb, cc[3] * wb);
            }
        }
    }
}

// ---------------- combine: out[t] = y[p0] + y[p1] ----------------------------
__global__ void combine_kernel(float* __restrict__ out, int T) {
    int idx = blockIdx.x * blockDim.x + threadIdx.x;
    int total = T * (D_DIM / 4);
    if (idx >= total) return;
    int t = idx / (D_DIM / 4);
    int d4 = idx - t * (D_DIM / 4);
    int p0 = g_slot_pos[2 * t];
    int p1 = g_slot_pos[2 * t + 1];
    const float4* y0 = (const float4*)(g_y + (size_t)p0 * D_DIM) + d4;
    const float4* y1 = (const float4*)(g_y + (size_t)p1 * D_DIM) + d4;
    float4 a = *y0, b = *y1;
    float4 r;
    r.x = a.x + b.x; r.y = a.y + b.y; r.z = a.z + b.z; r.w = a.w + b.w;
    ((float4*)out)[idx] = r;
}

// ---------------- launch -----------------------------------------------------
extern "C" void kernel_launch(void* const* d_in, const int* in_sizes, int n_in,
                              void* d_out, int out_size) {
    const float* x  = (const float*)d_in[0];
    const float* gw = (const float*)d_in[1];
    const float* w1 = (const float*)d_in[2];
    const float* w2 = (const float*)d_in[3];
    const float* w3 = (const float*)d_in[4];
    float* out = (float*)d_out;

    int T = in_sizes[0] / D_DIM;
    if (T > T_MAX) T = T_MAX;

    cudaFuncSetAttribute(gemm1_kernel, cudaFuncAttributeMaxDynamicSharedMemorySize, SMEM1);
    cudaFuncSetAttribute(gemm2_kernel, cudaFuncAttributeMaxDynamicSharedMemorySize, SMEM2);

    init_kernel<<<(NPOS + 255) / 256, 256>>>();
    prep_kernel<<<NB_GATE + NB_X + NB_W, 256>>>(x, gw, w1, w3, w2, T);
    offsets_kernel<<<1, 32>>>();
    scatter_kernel<<<(T * TOPK + 255) / 256, 256>>>(T);

    dim3 grid1(I_DIM / 64, NTILE);
    gemm1_kernel<<<grid1, 256, SMEM1>>>();

    dim3 grid2(D_DIM / 64, NTILE);
    gemm2_kernel<<<grid2, 256, SMEM2>>>();

    combine_kernel<<<(T * (D_DIM / 4) + 255) / 256, 256>>>(out, T);
}

// round 14
// speedup vs baseline: 1.2332x; 1.1871x over previous
#include <cuda_runtime.h>
#include <cuda_bf16.h>
#include <cstdint>
#include <math.h>

#define D_DIM 1024
#define I_DIM 4096
#define E_NUM 8
#define TOPK  2
#define T_MAX 2048
#define PADG  64
#define NPOS  (T_MAX*TOPK + E_NUM*128)    // 5120 upper bound
#define NTILE 44

// ---- GEMM1 stage (int8): A Qh/Ql 128r + B1 Qh/Ql 64r + B3 Qh/Ql 64r, 80B pitch
// each row holds 64 s8 (one K-chunk) in 64B data + 16B pad
#define STAGE1 40960
#define Q_AH   0
#define Q_AL   10240
#define Q_B1H  20480
#define Q_B1L  25600
#define Q_B3H  30720
#define Q_B3L  35840
#define SMEM1  (512 + 2*STAGE1)           // 82432

// ---- GEMM2 stage (bf16): A(h) 128r hi/lo + B(w2) 64r hi/lo -----------------
#define STAGE2 30720
#define O2_AH  0
#define O2_AL  10240
#define O2_BH  20480
#define O2_BL  25600
#define SMEM2  (3*STAGE2)                 // 92160, 2 CTAs/SM

// ---------------- scratch ----------------------------------------------------
__device__ int   g_counts[E_NUM];
__device__ int   g_offsets[E_NUM + 1];
__device__ int   g_cursor[E_NUM];
__device__ int   g_tile_expert[NTILE];
__device__ int   g_tile_r0[NTILE];
__device__ int   g_tile_rows[NTILE];
__device__ int   g_pos_token[NPOS];
__device__ float g_pos_wt[NPOS];
__device__ int   g_slot_pos[T_MAX * TOPK];
__device__ int   g_tok_eidx[T_MAX * TOPK];
__device__ float g_tok_ewt[T_MAX * TOPK];

// int8 two-level quantized operands for GEMM1
__device__ int8_t g_xqh[(size_t)T_MAX * D_DIM];
__device__ int8_t g_xql[(size_t)T_MAX * D_DIM];
__device__ float  g_xs[T_MAX];
__device__ int8_t g_w1qh[(size_t)E_NUM * I_DIM * D_DIM];
__device__ int8_t g_w1ql[(size_t)E_NUM * I_DIM * D_DIM];
__device__ int8_t g_w3qh[(size_t)E_NUM * I_DIM * D_DIM];
__device__ int8_t g_w3ql[(size_t)E_NUM * I_DIM * D_DIM];
__device__ float  g_w1s[E_NUM * I_DIM];
__device__ float  g_w3s[E_NUM * I_DIM];

// bf16 hi/lo for GEMM2 (unchanged path)
__device__ __nv_bfloat16 g_w2h[(size_t)E_NUM * D_DIM * I_DIM];
__device__ __nv_bfloat16 g_w2l[(size_t)E_NUM * D_DIM * I_DIM];
__device__ __nv_bfloat16 g_hh[(size_t)NPOS * I_DIM];
__device__ __nv_bfloat16 g_hl[(size_t)NPOS * I_DIM];
__device__ float g_y[(size_t)NPOS * D_DIM];

// ---------------- helpers ----------------------------------------------------
__device__ __forceinline__ uint32_t smem_u32(const void* p) {
    uint32_t a;
    asm("{ .reg .u64 t; cvta.to.shared.u64 t, %1; cvt.u32.u64 %0, t; }" : "=r"(a) : "l"(p));
    return a;
}
__device__ __forceinline__ void ldm_x4(uint32_t* r, uint32_t addr) {
    asm volatile("ldmatrix.sync.aligned.m8n8.x4.shared.b16 {%0,%1,%2,%3}, [%4];"
        : "=r"(r[0]), "=r"(r[1]), "=r"(r[2]), "=r"(r[3]) : "r"(addr));
}
__device__ __forceinline__ void mma_bf16(float* c, const uint32_t* a, uint32_t b0, uint32_t b1) {
    asm volatile("mma.sync.aligned.m16n8k16.row.col.f32.bf16.bf16.f32 "
        "{%0,%1,%2,%3}, {%4,%5,%6,%7}, {%8,%9}, {%0,%1,%2,%3};"
        : "+f"(c[0]), "+f"(c[1]), "+f"(c[2]), "+f"(c[3])
        : "r"(a[0]), "r"(a[1]), "r"(a[2]), "r"(a[3]), "r"(b0), "r"(b1));
}
__device__ __forceinline__ void mma_s8(int* c, const uint32_t* a, uint32_t b0, uint32_t b1) {
    asm volatile("mma.sync.aligned.m16n8k32.row.col.s32.s8.s8.s32 "
        "{%0,%1,%2,%3}, {%4,%5,%6,%7}, {%8,%9}, {%0,%1,%2,%3};"
        : "+r"(c[0]), "+r"(c[1]), "+r"(c[2]), "+r"(c[3])
        : "r"(a[0]), "r"(a[1]), "r"(a[2]), "r"(a[3]), "r"(b0), "r"(b1));
}
__device__ __forceinline__ void cp16(uint32_t dst, const void* src) {
    asm volatile("cp.async.cg.shared.global [%0], [%1], 16;" :: "r"(dst), "l"(src) : "memory");
}
__device__ __forceinline__ void cp16z(uint32_t dst, const void* src, int nbytes) {
    asm volatile("cp.async.cg.shared.global [%0], [%1], 16, %2;"
        :: "r"(dst), "l"(src), "r"(nbytes) : "memory");
}
__device__ __forceinline__ void cp_commit() {
    asm volatile("cp.async.commit_group;" ::: "memory");
}
template <int N>
__device__ __forceinline__ void cp_wait() {
    asm volatile("cp.async.wait_group %0;" :: "n"(N) : "memory");
}
__device__ __forceinline__ void split2(float a, float b, uint32_t& h, uint32_t& l) {
    __nv_bfloat162 hh = __floats2bfloat162_rn(a, b);
    __nv_bfloat162 ll = __floats2bfloat162_rn(a - __bfloat162float(hh.x),
                                              b - __bfloat162float(hh.y));
    h = reinterpret_cast<uint32_t&>(hh);
    l = reinterpret_cast<uint32_t&>(ll);
}

// ---------------- init -------------------------------------------------------
__global__ void init_kernel() {
    int i = blockIdx.x * blockDim.x + threadIdx.x;
    if (i < E_NUM) g_counts[i] = 0;
    if (i < NPOS) { g_pos_token[i] = -1; g_pos_wt[i] = 0.f; }
}

// ---------------- fused prep: gate + quantize x/w1/w3 + split w2 -------------
#define NB_GATE 256                       // T_MAX*32/256
#define NB_XQ   2048                      // one block per token row
#define NB_WQ   65536                     // 2 mats * 8 experts * 4096 rows
#define NB_W2   32768                     // E*D*I/4/256
__global__ void prep_kernel(const float* __restrict__ x,
                            const float* __restrict__ gw,
                            const float* __restrict__ w1,
                            const float* __restrict__ w3,
                            const float* __restrict__ w2,
                            int T) {
    __shared__ float red[8];
    int b = blockIdx.x;
    int tid = threadIdx.x;
    if (b < NB_GATE) {
        // ---- gate ----
        int gtid = b * 256 + tid;
        int warp = gtid >> 5, lane = gtid & 31;
        if (warp >= T) return;
        const float* xr = x + (size_t)warp * D_DIM;
        float acc[E_NUM];
#pragma unroll
        for (int e = 0; e < E_NUM; e++) acc[e] = 0.f;
        for (int k = lane; k < D_DIM; k += 32) {
            float xv = xr[k];
#pragma unroll
            for (int e = 0; e < E_NUM; e++)
                acc[e] = fmaf(xv, gw[e * D_DIM + k], acc[e]);
        }
#pragma unroll
        for (int e = 0; e < E_NUM; e++)
#pragma unroll
            for (int off = 16; off > 0; off >>= 1)
                acc[e] += __shfl_down_sync(0xFFFFFFFFu, acc[e], off);
        if (lane == 0) {
            int i0 = 0;
#pragma unroll
            for (int e = 1; e < E_NUM; e++) if (acc[e] > acc[i0]) i0 = e;
            int i1 = (i0 == 0) ? 1 : 0;
#pragma unroll
            for (int e = 0; e < E_NUM; e++)
                if (e != i0 && acc[e] > acc[i1]) i1 = e;
            float m = fmaxf(acc[i0], acc[i1]);
            float p0 = __expf(acc[i0] - m), p1 = __expf(acc[i1] - m);
            float s = p0 + p1;
            int base = warp * TOPK;
            g_tok_eidx[base + 0] = i0; g_tok_ewt[base + 0] = p0 / s;
            g_tok_eidx[base + 1] = i1; g_tok_ewt[base + 1] = p1 / s;
            atomicAdd(&g_counts[i0], 1);
            atomicAdd(&g_counts[i1], 1);
        }
    } else if (b < NB_GATE + NB_XQ + NB_WQ) {
        // ---- two-level int8 quantization of one 1024-elem row ----
        const float* src; int8_t* qh; int8_t* ql; float* sp;
        if (b < NB_GATE + NB_XQ) {
            int t = b - NB_GATE;
            if (t >= T) return;
            src = x + (size_t)t * D_DIM;
            qh = g_xqh + (size_t)t * D_DIM;
            ql = g_xql + (size_t)t * D_DIM;
            sp = g_xs + t;
        } else {
            int idx = b - NB_GATE - NB_XQ;           // [0, 65536)
            int mat = idx >> 15;                      // 0: w1, 1: w3
            int row = idx & 32767;                    // flattened e*I+col
            src = (mat ? w3 : w1) + (size_t)row * D_DIM;
            qh = (mat ? g_w3qh : g_w1qh) + (size_t)row * D_DIM;
            ql = (mat ? g_w3ql : g_w1ql) + (size_t)row * D_DIM;
            sp = (mat ? g_w3s : g_w1s) + row;
        }
        float4 v = ((const float4*)src)[tid];
        float am = fmaxf(fmaxf(fabsf(v.x), fabsf(v.y)), fmaxf(fabsf(v.z), fabsf(v.w)));
#pragma unroll
        for (int off = 16; off > 0; off >>= 1)
            am = fmaxf(am, __shfl_xor_sync(0xFFFFFFFFu, am, off));
        if ((tid & 31) == 0) red[tid >> 5] = am;
        __syncthreads();
        float m2 = red[0];
#pragma unroll
        for (int j = 1; j < 8; j++) m2 = fmaxf(m2, red[j]);
        float s = fmaxf(m2, 1e-20f) * (1.f / 127.f);
        float inv = 1.f / s;
        float t0 = v.x * inv, t1 = v.y * inv, t2 = v.z * inv, t3 = v.w * inv;
        float q0 = fminf(fmaxf(rintf(t0), -127.f), 127.f);
        float q1 = fminf(fmaxf(rintf(t1), -127.f), 127.f);
        float q2 = fminf(fmaxf(rintf(t2), -127.f), 127.f);
        float q3 = fminf(fmaxf(rintf(t3), -127.f), 127.f);
        float l0 = fminf(fmaxf(rintf((t0 - q0) * 128.f), -127.f), 127.f);
        float l1 = fminf(fmaxf(rintf((t1 - q1) * 128.f), -127.f), 127.f);
        float l2 = fminf(fmaxf(rintf((t2 - q2) * 128.f), -127.f), 127.f);
        float l3 = fminf(fmaxf(rintf((t3 - q3) * 128.f), -127.f), 127.f);
        ((char4*)qh)[tid] = make_char4((int)q0, (int)q1, (int)q2, (int)q3);
        ((char4*)ql)[tid] = make_char4((int)l0, (int)l1, (int)l2, (int)l3);
        if (tid == 0) *sp = s;
    } else {
        // ---- w2 bf16 hi/lo split ----
        int i = (b - NB_GATE - NB_XQ - NB_WQ) * 256 + tid;
        int n4 = E_NUM * I_DIM * D_DIM / 4;
        if (i >= n4) return;
        float4 v = ((const float4*)w2)[i];
        uint32_t h0, l0, h1, l1;
        split2(v.x, v.y, h0, l0);
        split2(v.z, v.w, h1, l1);
        ((uint2*)g_w2h)[i] = make_uint2(h0, h1);
        ((uint2*)g_w2l)[i] = make_uint2(l0, l1);
    }
}

// ---------------- offsets + tile table ---------------------------------------
__global__ void offsets_kernel() {
    if (threadIdx.x == 0 && blockIdx.x == 0) {
        int total = 0;
        for (int e = 0; e < E_NUM; e++) {
            g_offsets[e] = total;
            g_cursor[e]  = total;
            total += (g_counts[e] + PADG - 1) & ~(PADG - 1);
        }
        g_offsets[E_NUM] = total;
        int nt = 0;
        for (int e = 0; e < E_NUM; e++) {
            int sz = g_offsets[e + 1] - g_offsets[e];
            int r = 0;
            while (r < sz && nt < NTILE) {
                g_tile_expert[nt] = e;
                g_tile_r0[nt]     = g_offsets[e] + r;
                g_tile_rows[nt]   = (sz - r >= 128) ? 128 : 64;
                r += 128;
                nt++;
            }
        }
        for (int t = nt; t < NTILE; t++) g_tile_expert[t] = -1;
    }
}

__global__ void scatter_kernel(int T) {
    int idx = blockIdx.x * blockDim.x + threadIdx.x;
    if (idx >= T * TOPK) return;
    int e = g_tok_eidx[idx];
    int pos = atomicAdd(&g_cursor[e], 1);
    g_pos_token[pos] = idx >> 1;
    g_pos_wt[pos]    = g_tok_ewt[idx];
    g_slot_pos[idx]  = pos;
}

// ---------------- GEMM1 (int8 two-level): CTA 128x64, 16 warps ---------------
// warps 0-7: w1 path, warps 8-15: w3 path; warp tile m32 x n32
__global__ __launch_bounds__(512, 1)
void gemm1_kernel() {
    extern __shared__ __align__(128) char sm[];
    int e = g_tile_expert[blockIdx.y];
    if (e < 0) return;
    int tid = threadIdx.x, lane = tid & 31, wid = tid >> 5;
    int r0 = g_tile_r0[blockIdx.y];
    int rows = g_tile_rows[blockIdx.y];
    int c0 = blockIdx.x * 64;
    int* s_tok = (int*)sm;
    uint32_t tiles_u = smem_u32(sm) + 512;

    if (tid < 128) s_tok[tid] = (tid < rows) ? g_pos_token[r0 + tid] : -1;
    __syncthreads();

    int is3 = wid >> 3;
    int wl = wid & 7;
    int mrow = (wl >> 1) * 32;
    int ncol = (wl & 1) * 32;
    bool act = (mrow < rows);

    int chh[2][4][4], ccr[2][4][4];
#pragma unroll
    for (int a = 0; a < 2; a++)
#pragma unroll
        for (int b = 0; b < 4; b++)
#pragma unroll
            for (int q = 0; q < 4; q++) { chh[a][b][q] = 0; ccr[a][b][q] = 0; }

    auto issue_stage = [&](int kc, int st) {
        uint32_t base = tiles_u + st * STAGE1;
        int kb = kc * 64;   // s8 elements
#pragma unroll
        for (int it = 0; it < 4; it++) {
            int gid = it * 512 + tid;
            if (gid < 1024) {
                int hl = gid >> 9, g = gid & 511;
                int r = g >> 2, cc = g & 3;
                int tok = s_tok[r];
                const int8_t* spq = (hl ? g_xql : g_xqh)
                    + ((size_t)(tok >= 0 ? tok : 0) * D_DIM + kb + cc * 16);
                cp16z(base + (hl ? Q_AL : Q_AH) + r * 80 + cc * 16, spq,
                      tok >= 0 ? 16 : 0);
            } else {
                int g2 = gid - 1024;
                int mat = g2 >> 9, g3 = g2 & 511;
                int hl = g3 >> 8, r = (g3 >> 2) & 63, cc = g3 & 3;
                const int8_t* wq = mat ? (hl ? g_w3ql : g_w3qh)
                                       : (hl ? g_w1ql : g_w1qh);
                const int8_t* spq = wq
                    + (((size_t)e * I_DIM + c0 + r) * D_DIM + kb + cc * 16);
                uint32_t off = (mat ? Q_B3H : Q_B1H) + (hl ? 5120u : 0u)
                             + r * 80 + cc * 16;
                cp16(base + off, spq);
            }
        }
    };

    auto compute = [&](int st) {
        if (!act) return;
        uint32_t su = tiles_u + st * STAGE1;
        uint32_t bb = su + (is3 ? Q_B3H : Q_B1H);
#pragma unroll
        for (int ks = 0; ks < 2; ks++) {       // two k32 steps per 64-chunk
            int ko = ks * 32;
            uint32_t ah[2][4], al[2][4];
#pragma unroll
            for (int mt = 0; mt < 2; mt++) {
                uint32_t aaddr = su + Q_AH
                    + (uint32_t)((mrow + mt * 16 + (lane & 15)) * 80 + ko + (lane >> 4) * 16);
                ldm_x4(ah[mt], aaddr);
                ldm_x4(al[mt], aaddr + (Q_AL - Q_AH));
            }
#pragma unroll
            for (int nt = 0; nt < 2; nt++) {
                uint32_t bh[4], bl[4];
                uint32_t baddr = bb
                    + (uint32_t)((ncol + nt * 16 + (lane & 15)) * 80 + ko + (lane >> 4) * 16);
                ldm_x4(bh, baddr);
                ldm_x4(bl, baddr + 5120);
#pragma unroll
                for (int mt = 0; mt < 2; mt++)
#pragma unroll
                    for (int sub = 0; sub < 2; sub++) {
                        int* cc1 = chh[mt][nt * 2 + sub];
                        int* cc2 = ccr[mt][nt * 2 + sub];
                        mma_s8(cc1, ah[mt], bh[sub], bh[sub + 2]);
                        mma_s8(cc2, al[mt], bh[sub], bh[sub + 2]);
                        mma_s8(cc2, ah[mt], bl[sub], bl[sub + 2]);
                    }
            }
        }
    };

    issue_stage(0, 0); cp_commit();
    issue_stage(1, 1); cp_commit();
#pragma unroll 1
    for (int kc = 0; kc < 16; kc++) {
        if (kc < 15) cp_wait<1>(); else cp_wait<0>();
        __syncthreads();
        compute(kc & 1);
        __syncthreads();
        if (kc + 2 < 16) { issue_stage(kc + 2, kc & 1); cp_commit(); }
    }

    // epilogue: w3 warps write d3 to smem (stage-0 area, disjoint from stage-1
    // reads); then w1 warps fuse silu and emit bf16 hi/lo h
    float* stg = (float*)(sm + 512);   // [128][68]
    const float* ws = is3 ? g_w3s : g_w1s;
    if (is3 && act) {
#pragma unroll
        for (int mt = 0; mt < 2; mt++) {
            int rowa = mrow + mt * 16 + (lane >> 2);
            int ta = s_tok[rowa], tb = s_tok[rowa + 8];
            float sxa = (ta >= 0) ? g_xs[ta] : 0.f;
            float sxb = (tb >= 0) ? g_xs[tb] : 0.f;
#pragma unroll
            for (int ns = 0; ns < 4; ns++) {
                int colloc = ncol + ns * 8 + 2 * (lane & 3);
                int col = c0 + colloc;
                float sw0 = ws[e * I_DIM + col];
                float sw1 = ws[e * I_DIM + col + 1];
                int* hh = chh[mt][ns]; int* cr = ccr[mt][ns];
                float d0 = sxa * sw0 * fmaf((float)cr[0], 0.0078125f, (float)hh[0]);
                float d1 = sxa * sw1 * fmaf((float)cr[1], 0.0078125f, (float)hh[1]);
                float d2 = sxb * sw0 * fmaf((float)cr[2], 0.0078125f, (float)hh[2]);
                float d3 = sxb * sw1 * fmaf((float)cr[3], 0.0078125f, (float)hh[3]);
                *(float2*)&stg[rowa * 68 + colloc]       = make_float2(d0, d1);
                *(float2*)&stg[(rowa + 8) * 68 + colloc] = make_float2(d2, d3);
            }
        }
    }
    __syncthreads();
    if (!is3 && act) {
#pragma unroll
        for (int mt = 0; mt < 2; mt++) {
            int rowa = mrow + mt * 16 + (lane >> 2);
            int ta = s_tok[rowa], tb = s_tok[rowa + 8];
            float sxa = (ta >= 0) ? g_xs[ta] : 0.f;
            float sxb = (tb >= 0) ? g_xs[tb] : 0.f;
#pragma unroll
            for (int ns = 0; ns < 4; ns++) {
                int colloc = ncol + ns * 8 + 2 * (lane & 3);
                int col = c0 + colloc;
                float sw0 = ws[e * I_DIM + col];
                float sw1 = ws[e * I_DIM + col + 1];
                int* hh = chh[mt][ns]; int* cr = ccr[mt][ns];
                float d0 = sxa * sw0 * fmaf((float)cr[0], 0.0078125f, (float)hh[0]);
                float d1 = sxa * sw1 * fmaf((float)cr[1], 0.0078125f, (float)hh[1]);
                float d2 = sxb * sw0 * fmaf((float)cr[2], 0.0078125f, (float)hh[2]);
                float d3 = sxb * sw1 * fmaf((float)cr[3], 0.0078125f, (float)hh[3]);
                float2 e3a = *(float2*)&stg[rowa * 68 + colloc];
                float2 e3b = *(float2*)&stg[(rowa + 8) * 68 + colloc];
                float v0 = d0 * e3a.x / (1.f + __expf(-d0));
                float v1 = d1 * e3a.y / (1.f + __expf(-d1));
                float v2 = d2 * e3b.x / (1.f + __expf(-d2));
                float v3 = d3 * e3b.y / (1.f + __expf(-d3));
                uint32_t ha, la, hb, lb;
                split2(v0, v1, ha, la);
                split2(v2, v3, hb, lb);
                size_t o0 = (size_t)(r0 + rowa) * I_DIM + col;
                size_t o1 = (size_t)(r0 + rowa + 8) * I_DIM + col;
                *(uint32_t*)(g_hh + o0) = ha;
                *(uint32_t*)(g_hl + o0) = la;
                *(uint32_t*)(g_hh + o1) = hb;
                *(uint32_t*)(g_hl + o1) = lb;
            }
        }
    }
}

// ---------------- GEMM2 (bf16 3-term, unchanged from R13) --------------------
__global__ __launch_bounds__(256, 2)
void gemm2_kernel() {
    extern __shared__ __align__(128) char sm[];
    int e = g_tile_expert[blockIdx.y];
    if (e < 0) return;
    int tid = threadIdx.x, lane = tid & 31, wid = tid >> 5;
    int r0 = g_tile_r0[blockIdx.y];
    int rows = g_tile_rows[blockIdx.y];
    int c0 = blockIdx.x * 64;
    uint32_t tiles_u = smem_u32(sm);

    int mrow = (wid >> 1) * 32;
    int ncol = (wid & 1) * 32;
    bool act = (mrow < rows);

    float c[2][4][4];
#pragma unroll
    for (int a = 0; a < 2; a++)
#pragma unroll
        for (int b = 0; b < 4; b++)
#pragma unroll
            for (int q = 0; q < 4; q++) c[a][b][q] = 0.f;

    auto issue_stage = [&](int kc, int st) {
        uint32_t base = tiles_u + st * STAGE2;
        int kb = kc * 32;
#pragma unroll
        for (int it = 0; it < 6; it++) {
            int gid = it * 256 + tid;
            if (gid < 1024) {
                int hl = gid >> 9, r = (gid >> 2) & 127, cc = gid & 3;
                const __nv_bfloat16* bp = hl ? g_hl : g_hh;
                const __nv_bfloat16* sp = bp
                    + ((size_t)(r0 + r) * I_DIM + kb + cc * 8);
                cp16(base + (hl ? O2_AL : O2_AH) + r * 80 + cc * 16, sp);
            } else {
                int g2 = gid - 1024;
                int hl = g2 >> 8, r = (g2 >> 2) & 63, cc = g2 & 3;
                const __nv_bfloat16* wp = hl ? g_w2l : g_w2h;
                const __nv_bfloat16* sp = wp
                    + (((size_t)e * D_DIM + c0 + r) * I_DIM + kb + cc * 8);
                cp16(base + (hl ? O2_BL : O2_BH) + r * 80 + cc * 16, sp);
            }
        }
    };

    auto compute = [&](int st) {
        if (!act) return;
        uint32_t su = tiles_u + st * STAGE2;
#pragma unroll
        for (int kk = 0; kk < 2; kk++) {
            int ko = kk * 32;
            uint32_t ah[2][4], al[2][4];
#pragma unroll
            for (int mt = 0; mt < 2; mt++) {
                uint32_t aaddr = su
                    + (uint32_t)((mrow + mt * 16 + (lane & 15)) * 80 + ko + (lane >> 4) * 16);
                ldm_x4(ah[mt], aaddr);
                ldm_x4(al[mt], aaddr + 10240);
            }
#pragma unroll
            for (int nt = 0; nt < 2; nt++) {
                uint32_t bh[4], bl[4];
                uint32_t baddr = su + O2_BH
                    + (uint32_t)((ncol + nt * 16 + (lane & 15)) * 80 + ko + (lane >> 4) * 16);
                ldm_x4(bh, baddr);
                ldm_x4(bl, baddr + 5120);
#pragma unroll
                for (int mt = 0; mt < 2; mt++)
#pragma unroll
                    for (int sub = 0; sub < 2; sub++) {
                        float* cc = c[mt][nt * 2 + sub];
                        mma_bf16(cc, ah[mt], bh[sub], bh[sub + 2]);
                        mma_bf16(cc, al[mt], bh[sub], bh[sub + 2]);
                        mma_bf16(cc, ah[mt], bl[sub], bl[sub + 2]);
                    }
            }
        }
    };

    issue_stage(0, 0); cp_commit();
    issue_stage(1, 1); cp_commit();
#pragma unroll 1
    for (int kc = 0; kc < 128; kc++) {
        if (kc < 127) cp_wait<1>(); else cp_wait<0>();
        __syncthreads();
        if (kc + 2 < 128) { issue_stage(kc + 2, (kc + 2) % 3); cp_commit(); }
        compute(kc % 3);
    }

    if (act) {
#pragma unroll
        for (int mt = 0; mt < 2; mt++) {
            int row = mrow + mt * 16 + (lane >> 2);
            float wa = g_pos_wt[r0 + row];
            float wb = g_pos_wt[r0 + row + 8];
#pragma unroll
            for (int ns = 0; ns < 4; ns++) {
                int col = c0 + ncol + ns * 8 + 2 * (lane & 3);
                float* cc = c[mt][ns];
                *(float2*)(g_y + (size_t)(r0 + row) * D_DIM + col)
                    = make_float2(cc[0] * wa, cc[1] * wa);
                *(float2*)(g_y + (size_t)(r0 + row + 8) * D_DIM + col)
                    = make_float2(cc[2] * wb, cc[3] * wb);
            }
        }
    }
}

// ---------------- combine ----------------------------------------------------
__global__ void combine_kernel(float* __restrict__ out, int T) {
    int idx = blockIdx.x * blockDim.x + threadIdx.x;
    int total = T * (D_DIM / 4);
    if (idx >= total) return;
    int t = idx / (D_DIM / 4);
    int d4 = idx - t * (D_DIM / 4);
    int p0 = g_slot_pos[2 * t];
    int p1 = g_slot_pos[2 * t + 1];
    const float4* y0 = (const float4*)(g_y + (size_t)p0 * D_DIM) + d4;
    const float4* y1 = (const float4*)(g_y + (size_t)p1 * D_DIM) + d4;
    float4 a = *y0, b = *y1;
    float4 r;
    r.x = a.x + b.x; r.y = a.y + b.y; r.z = a.z + b.z; r.w = a.w + b.w;
    ((float4*)out)[idx] = r;
}

// ---------------- launch -----------------------------------------------------
extern "C" void kernel_launch(void* const* d_in, const int* in_sizes, int n_in,
                              void* d_out, int out_size) {
    const float* x  = (const float*)d_in[0];
    const float* gw = (const float*)d_in[1];
    const float* w1 = (const float*)d_in[2];
    const float* w2 = (const float*)d_in[3];
    const float* w3 = (const float*)d_in[4];
    float* out = (float*)d_out;

    int T = in_sizes[0] / D_DIM;
    if (T > T_MAX) T = T_MAX;

    cudaFuncSetAttribute(gemm1_kernel, cudaFuncAttributeMaxDynamicSharedMemorySize, SMEM1);
    cudaFuncSetAttribute(gemm2_kernel, cudaFuncAttributeMaxDynamicSharedMemorySize, SMEM2);

    init_kernel<<<(NPOS + 255) / 256, 256>>>();
    prep_kernel<<<NB_GATE + NB_XQ + NB_WQ + NB_W2, 256>>>(x, gw, w1, w3, w2, T);
    offsets_kernel<<<1, 32>>>();
    scatter_kernel<<<(T * TOPK + 255) / 256, 256>>>(T);

    dim3 grid1(I_DIM / 64, NTILE);
    gemm1_kernel<<<grid1, 512, SMEM1>>>();

    dim3 grid2(D_DIM / 64, NTILE);
    gemm2_kernel<<<grid2, 256, SMEM2>>>();

    combine_kernel<<<(T * (D_DIM / 4) + 255) / 256, 256>>>(out, T);
}

// round 15
// speedup vs baseline: 1.3735x; 1.1137x over previous
#include <cuda_runtime.h>
#include <cuda_bf16.h>
#include <cstdint>
#include <math.h>

#define D_DIM 1024
#define I_DIM 4096
#define E_NUM 8
#define TOPK  2
#define T_MAX 2048
#define PADG  64
#define NPOS  (T_MAX*TOPK + E_NUM*128)    // 5120 upper bound
#define NTILE 44
#define NCHUNK (I_DIM/64)                 // 64 K-chunks of h

// ---- GEMM1 stage (int8): A Qh/Ql 128r + B1 Qh/Ql 64r + B3 Qh/Ql 64r, 80B pitch
#define STAGE1 40960
#define Q_AH   0
#define Q_AL   10240
#define Q_B1H  20480
#define Q_B1L  25600
#define Q_B3H  30720
#define Q_B3L  35840
#define SMEM1  (512 + 2*STAGE1)           // 82432

// ---- GEMM2 stage (int8): A(h) Qh/Ql 128r + B(w2) Qh/Ql 64r + A-scales ------
#define STAGE2Q 31232
#define H_AH   0
#define H_AL   10240
#define H_BH   20480
#define H_BL   25600
#define H_AS   30720                      // 128 fp32 per-row chunk scales
#define SMEM2  (2*STAGE2Q)                // 62464

// ---------------- scratch ----------------------------------------------------
__device__ int   g_counts[E_NUM];
__device__ int   g_offsets[E_NUM + 1];
__device__ int   g_cursor[E_NUM];
__device__ int   g_tile_expert[NTILE];
__device__ int   g_tile_r0[NTILE];
__device__ int   g_tile_rows[NTILE];
__device__ int   g_pos_token[NPOS];
__device__ float g_pos_wt[NPOS];
__device__ int   g_slot_pos[T_MAX * TOPK];
__device__ int   g_tok_eidx[T_MAX * TOPK];
__device__ float g_tok_ewt[T_MAX * TOPK];

// int8 two-level quantized operands for GEMM1
__device__ int8_t g_xqh[(size_t)T_MAX * D_DIM];
__device__ int8_t g_xql[(size_t)T_MAX * D_DIM];
__device__ float  g_xs[T_MAX];
__device__ int8_t g_w1qh[(size_t)E_NUM * I_DIM * D_DIM];
__device__ int8_t g_w1ql[(size_t)E_NUM * I_DIM * D_DIM];
__device__ int8_t g_w3qh[(size_t)E_NUM * I_DIM * D_DIM];
__device__ int8_t g_w3ql[(size_t)E_NUM * I_DIM * D_DIM];
__device__ float  g_w1s[E_NUM * I_DIM];
__device__ float  g_w3s[E_NUM * I_DIM];

// int8 two-level operands for GEMM2
__device__ int8_t g_w2qh[(size_t)E_NUM * D_DIM * I_DIM];
__device__ int8_t g_w2ql[(size_t)E_NUM * D_DIM * I_DIM];
__device__ float  g_w2s[E_NUM * D_DIM];
__device__ int8_t g_hqh[(size_t)NPOS * I_DIM];
__device__ int8_t g_hql[(size_t)NPOS * I_DIM];
__device__ float  g_hs[(size_t)NCHUNK * NPOS];   // [chunk][pos]
__device__ float  g_y[(size_t)NPOS * D_DIM];

// ---------------- helpers ----------------------------------------------------
__device__ __forceinline__ uint32_t smem_u32(const void* p) {
    uint32_t a;
    asm("{ .reg .u64 t; cvta.to.shared.u64 t, %1; cvt.u32.u64 %0, t; }" : "=r"(a) : "l"(p));
    return a;
}
__device__ __forceinline__ void ldm_x4(uint32_t* r, uint32_t addr) {
    asm volatile("ldmatrix.sync.aligned.m8n8.x4.shared.b16 {%0,%1,%2,%3}, [%4];"
        : "=r"(r[0]), "=r"(r[1]), "=r"(r[2]), "=r"(r[3]) : "r"(addr));
}
__device__ __forceinline__ void mma_s8(int* c, const uint32_t* a, uint32_t b0, uint32_t b1) {
    asm volatile("mma.sync.aligned.m16n8k32.row.col.s32.s8.s8.s32 "
        "{%0,%1,%2,%3}, {%4,%5,%6,%7}, {%8,%9}, {%0,%1,%2,%3};"
        : "+r"(c[0]), "+r"(c[1]), "+r"(c[2]), "+r"(c[3])
        : "r"(a[0]), "r"(a[1]), "r"(a[2]), "r"(a[3]), "r"(b0), "r"(b1));
}
__device__ __forceinline__ void cp16(uint32_t dst, const void* src) {
    asm volatile("cp.async.cg.shared.global [%0], [%1], 16;" :: "r"(dst), "l"(src) : "memory");
}
__device__ __forceinline__ void cp16z(uint32_t dst, const void* src, int nbytes) {
    asm volatile("cp.async.cg.shared.global [%0], [%1], 16, %2;"
        :: "r"(dst), "l"(src), "r"(nbytes) : "memory");
}
__device__ __forceinline__ void cp_commit() {
    asm volatile("cp.async.commit_group;" ::: "memory");
}
template <int N>
__device__ __forceinline__ void cp_wait() {
    asm volatile("cp.async.wait_group %0;" :: "n"(N) : "memory");
}
__device__ __forceinline__ void quant2(float v, float inv, int& q, int& ql) {
    float t = v * inv;
    float qf = fminf(fmaxf(rintf(t), -127.f), 127.f);
    q = (int)qf;
    ql = (int)fminf(fmaxf(rintf((t - qf) * 128.f), -127.f), 127.f);
}
__device__ __forceinline__ unsigned short pack2(int a, int b) {
    return (unsigned short)((a & 0xFF) | ((b & 0xFF) << 8));
}

// ---------------- init -------------------------------------------------------
__global__ void init_kernel() {
    int i = blockIdx.x * blockDim.x + threadIdx.x;
    if (i < E_NUM) g_counts[i] = 0;
    if (i < NPOS) { g_pos_token[i] = -1; g_pos_wt[i] = 0.f; }
}

// ---------------- fused prep: gate + quant x/w1/w3 (1024-rows) + quant w2 ----
#define NB_GATE 256                       // T_MAX*32/256
#define NB_XQ   2048
#define NB_WQ   65536                     // 2 mats * 8 experts * 4096 rows
#define NB_W2   8192                      // E*D rows of length I
__global__ void prep_kernel(const float* __restrict__ x,
                            const float* __restrict__ gw,
                            const float* __restrict__ w1,
                            const float* __restrict__ w3,
                            const float* __restrict__ w2,
                            int T) {
    __shared__ float red[8];
    int b = blockIdx.x;
    int tid = threadIdx.x;
    if (b < NB_GATE) {
        // ---- gate ----
        int gtid = b * 256 + tid;
        int warp = gtid >> 5, lane = gtid & 31;
        if (warp >= T) return;
        const float* xr = x + (size_t)warp * D_DIM;
        float acc[E_NUM];
#pragma unroll
        for (int e = 0; e < E_NUM; e++) acc[e] = 0.f;
        for (int k = lane; k < D_DIM; k += 32) {
            float xv = xr[k];
#pragma unroll
            for (int e = 0; e < E_NUM; e++)
                acc[e] = fmaf(xv, gw[e * D_DIM + k], acc[e]);
        }
#pragma unroll
        for (int e = 0; e < E_NUM; e++)
#pragma unroll
            for (int off = 16; off > 0; off >>= 1)
                acc[e] += __shfl_down_sync(0xFFFFFFFFu, acc[e], off);
        if (lane == 0) {
            int i0 = 0;
#pragma unroll
            for (int e = 1; e < E_NUM; e++) if (acc[e] > acc[i0]) i0 = e;
            int i1 = (i0 == 0) ? 1 : 0;
#pragma unroll
            for (int e = 0; e < E_NUM; e++)
                if (e != i0 && acc[e] > acc[i1]) i1 = e;
            float m = fmaxf(acc[i0], acc[i1]);
            float p0 = __expf(acc[i0] - m), p1 = __expf(acc[i1] - m);
            float s = p0 + p1;
            int base = warp * TOPK;
            g_tok_eidx[base + 0] = i0; g_tok_ewt[base + 0] = p0 / s;
            g_tok_eidx[base + 1] = i1; g_tok_ewt[base + 1] = p1 / s;
            atomicAdd(&g_counts[i0], 1);
            atomicAdd(&g_counts[i1], 1);
        }
    } else if (b < NB_GATE + NB_XQ + NB_WQ) {
        // ---- two-level int8 quantization of one 1024-elem row ----
        const float* src; int8_t* qh; int8_t* ql; float* sp;
        if (b < NB_GATE + NB_XQ) {
            int t = b - NB_GATE;
            if (t >= T) return;
            src = x + (size_t)t * D_DIM;
            qh = g_xqh + (size_t)t * D_DIM;
            ql = g_xql + (size_t)t * D_DIM;
            sp = g_xs + t;
        } else {
            int idx = b - NB_GATE - NB_XQ;
            int mat = idx >> 15;
            int row = idx & 32767;
            src = (mat ? w3 : w1) + (size_t)row * D_DIM;
            qh = (mat ? g_w3qh : g_w1qh) + (size_t)row * D_DIM;
            ql = (mat ? g_w3ql : g_w1ql) + (size_t)row * D_DIM;
            sp = (mat ? g_w3s : g_w1s) + row;
        }
        float4 v = ((const float4*)src)[tid];
        float am = fmaxf(fmaxf(fabsf(v.x), fabsf(v.y)), fmaxf(fabsf(v.z), fabsf(v.w)));
#pragma unroll
        for (int off = 16; off > 0; off >>= 1)
            am = fmaxf(am, __shfl_xor_sync(0xFFFFFFFFu, am, off));
        if ((tid & 31) == 0) red[tid >> 5] = am;
        __syncthreads();
        float m2 = red[0];
#pragma unroll
        for (int j = 1; j < 8; j++) m2 = fmaxf(m2, red[j]);
        float s = fmaxf(m2, 1e-20f) * (1.f / 127.f);
        float inv = 1.f / s;
        int q0, l0, q1, l1, q2, l2, q3, l3;
        quant2(v.x, inv, q0, l0); quant2(v.y, inv, q1, l1);
        quant2(v.z, inv, q2, l2); quant2(v.w, inv, q3, l3);
        ((char4*)qh)[tid] = make_char4(q0, q1, q2, q3);
        ((char4*)ql)[tid] = make_char4(l0, l1, l2, l3);
        if (tid == 0) *sp = s;
    } else {
        // ---- per-row two-level quant of w2 (rows of length I=4096) ----
        int row = b - NB_GATE - NB_XQ - NB_WQ;   // [0, E*D)
        const float* src = w2 + (size_t)row * I_DIM;
        float4 v[4];
        float am = 0.f;
#pragma unroll
        for (int i = 0; i < 4; i++) {
            v[i] = ((const float4*)src)[tid + i * 256];
            am = fmaxf(am, fmaxf(fmaxf(fabsf(v[i].x), fabsf(v[i].y)),
                                 fmaxf(fabsf(v[i].z), fabsf(v[i].w))));
        }
#pragma unroll
        for (int off = 16; off > 0; off >>= 1)
            am = fmaxf(am, __shfl_xor_sync(0xFFFFFFFFu, am, off));
        if ((tid & 31) == 0) red[tid >> 5] = am;
        __syncthreads();
        float m2 = red[0];
#pragma unroll
        for (int j = 1; j < 8; j++) m2 = fmaxf(m2, red[j]);
        float s = fmaxf(m2, 1e-20f) * (1.f / 127.f);
        float inv = 1.f / s;
#pragma unroll
        for (int i = 0; i < 4; i++) {
            int q0, l0, q1, l1, q2, l2, q3, l3;
            quant2(v[i].x, inv, q0, l0); quant2(v[i].y, inv, q1, l1);
            quant2(v[i].z, inv, q2, l2); quant2(v[i].w, inv, q3, l3);
            ((char4*)(g_w2qh + (size_t)row * I_DIM))[tid + i * 256]
                = make_char4(q0, q1, q2, q3);
            ((char4*)(g_w2ql + (size_t)row * I_DIM))[tid + i * 256]
                = make_char4(l0, l1, l2, l3);
        }
        if (tid == 0) g_w2s[row] = s;
    }
}

// ---------------- offsets + tile table ---------------------------------------
__global__ void offsets_kernel() {
    if (threadIdx.x == 0 && blockIdx.x == 0) {
        int total = 0;
        for (int e = 0; e < E_NUM; e++) {
            g_offsets[e] = total;
            g_cursor[e]  = total;
            total += (g_counts[e] + PADG - 1) & ~(PADG - 1);
        }
        g_offsets[E_NUM] = total;
        int nt = 0;
        for (int e = 0; e < E_NUM; e++) {
            int sz = g_offsets[e + 1] - g_offsets[e];
            int r = 0;
            while (r < sz && nt < NTILE) {
                g_tile_expert[nt] = e;
                g_tile_r0[nt]     = g_offsets[e] + r;
                g_tile_rows[nt]   = (sz - r >= 128) ? 128 : 64;
                r += 128;
                nt++;
            }
        }
        for (int t = nt; t < NTILE; t++) g_tile_expert[t] = -1;
    }
}

__global__ void scatter_kernel(int T) {
    int idx = blockIdx.x * blockDim.x + threadIdx.x;
    if (idx >= T * TOPK) return;
    int e = g_tok_eidx[idx];
    int pos = atomicAdd(&g_cursor[e], 1);
    g_pos_token[pos] = idx >> 1;
    g_pos_wt[pos]    = g_tok_ewt[idx];
    g_slot_pos[idx]  = pos;
}

// ---------------- GEMM1 (int8 two-level): CTA 128x64, 16 warps ---------------
__global__ __launch_bounds__(512, 1)
void gemm1_kernel() {
    extern __shared__ __align__(128) char sm[];
    int e = g_tile_expert[blockIdx.y];
    if (e < 0) return;
    int tid = threadIdx.x, lane = tid & 31, wid = tid >> 5;
    int r0 = g_tile_r0[blockIdx.y];
    int rows = g_tile_rows[blockIdx.y];
    int c0 = blockIdx.x * 64;
    int* s_tok = (int*)sm;
    uint32_t tiles_u = smem_u32(sm) + 512;

    if (tid < 128) s_tok[tid] = (tid < rows) ? g_pos_token[r0 + tid] : -1;
    __syncthreads();

    int is3 = wid >> 3;
    int wl = wid & 7;
    int mrow = (wl >> 1) * 32;
    int ncol = (wl & 1) * 32;
    bool act = (mrow < rows);

    int chh[2][4][4], ccr[2][4][4];
#pragma unroll
    for (int a = 0; a < 2; a++)
#pragma unroll
        for (int b = 0; b < 4; b++)
#pragma unroll
            for (int q = 0; q < 4; q++) { chh[a][b][q] = 0; ccr[a][b][q] = 0; }

    auto issue_stage = [&](int kc, int st) {
        uint32_t base = tiles_u + st * STAGE1;
        int kb = kc * 64;
#pragma unroll
        for (int it = 0; it < 4; it++) {
            int gid = it * 512 + tid;
            if (gid < 1024) {
                int hl = gid >> 9, g = gid & 511;
                int r = g >> 2, cc = g & 3;
                int tok = s_tok[r];
                const int8_t* spq = (hl ? g_xql : g_xqh)
                    + ((size_t)(tok >= 0 ? tok : 0) * D_DIM + kb + cc * 16);
                cp16z(base + (hl ? Q_AL : Q_AH) + r * 80 + cc * 16, spq,
                      tok >= 0 ? 16 : 0);
            } else {
                int g2 = gid - 1024;
                int mat = g2 >> 9, g3 = g2 & 511;
                int hl = g3 >> 8, r = (g3 >> 2) & 63, cc = g3 & 3;
                const int8_t* wq = mat ? (hl ? g_w3ql : g_w3qh)
                                       : (hl ? g_w1ql : g_w1qh);
                const int8_t* spq = wq
                    + (((size_t)e * I_DIM + c0 + r) * D_DIM + kb + cc * 16);
                uint32_t off = (mat ? Q_B3H : Q_B1H) + (hl ? 5120u : 0u)
                             + r * 80 + cc * 16;
                cp16(base + off, spq);
            }
        }
    };

    auto compute = [&](int st) {
        if (!act) return;
        uint32_t su = tiles_u + st * STAGE1;
        uint32_t bb = su + (is3 ? Q_B3H : Q_B1H);
#pragma unroll
        for (int ks = 0; ks < 2; ks++) {
            int ko = ks * 32;
            uint32_t ah[2][4], al[2][4];
#pragma unroll
            for (int mt = 0; mt < 2; mt++) {
                uint32_t aaddr = su + Q_AH
                    + (uint32_t)((mrow + mt * 16 + (lane & 15)) * 80 + ko + (lane >> 4) * 16);
                ldm_x4(ah[mt], aaddr);
                ldm_x4(al[mt], aaddr + (Q_AL - Q_AH));
            }
#pragma unroll
            for (int nt = 0; nt < 2; nt++) {
                uint32_t bh[4], bl[4];
                uint32_t baddr = bb
                    + (uint32_t)((ncol + nt * 16 + (lane & 15)) * 80 + ko + (lane >> 4) * 16);
                ldm_x4(bh, baddr);
                ldm_x4(bl, baddr + 5120);
#pragma unroll
                for (int mt = 0; mt < 2; mt++)
#pragma unroll
                    for (int sub = 0; sub < 2; sub++) {
                        int* cc1 = chh[mt][nt * 2 + sub];
                        int* cc2 = ccr[mt][nt * 2 + sub];
                        mma_s8(cc1, ah[mt], bh[sub], bh[sub + 2]);
                        mma_s8(cc2, al[mt], bh[sub], bh[sub + 2]);
                        mma_s8(cc2, ah[mt], bl[sub], bl[sub + 2]);
                    }
            }
        }
    };

    issue_stage(0, 0); cp_commit();
    issue_stage(1, 1); cp_commit();
#pragma unroll 1
    for (int kc = 0; kc < 16; kc++) {
        if (kc < 15) cp_wait<1>(); else cp_wait<0>();
        __syncthreads();
        compute(kc & 1);
        __syncthreads();
        if (kc + 2 < 16) { issue_stage(kc + 2, kc & 1); cp_commit(); }
    }

    // epilogue: d3 exchange, silu, per-(row,chunk) two-level int8 quant of h
    float* stg    = (float*)(sm + 512);            // [128][68] d3 exchange
    float* s_amax = (float*)(sm + 512 + 34816);    // 128 row absmax
    if (tid < 128) s_amax[tid] = 0.f;
    const float* ws = is3 ? g_w3s : g_w1s;
    if (is3 && act) {
#pragma unroll
        for (int mt = 0; mt < 2; mt++) {
            int rowa = mrow + mt * 16 + (lane >> 2);
            int ta = s_tok[rowa], tb = s_tok[rowa + 8];
            float sxa = (ta >= 0) ? g_xs[ta] : 0.f;
            float sxb = (tb >= 0) ? g_xs[tb] : 0.f;
#pragma unroll
            for (int ns = 0; ns < 4; ns++) {
                int colloc = ncol + ns * 8 + 2 * (lane & 3);
                int col = c0 + colloc;
                float sw0 = ws[e * I_DIM + col];
                float sw1 = ws[e * I_DIM + col + 1];
                int* hh = chh[mt][ns]; int* cr = ccr[mt][ns];
                float d0 = sxa * sw0 * fmaf((float)cr[0], 0.0078125f, (float)hh[0]);
                float d1 = sxa * sw1 * fmaf((float)cr[1], 0.0078125f, (float)hh[1]);
                float d2 = sxb * sw0 * fmaf((float)cr[2], 0.0078125f, (float)hh[2]);
                float d3 = sxb * sw1 * fmaf((float)cr[3], 0.0078125f, (float)hh[3]);
                *(float2*)&stg[rowa * 68 + colloc]       = make_float2(d0, d1);
                *(float2*)&stg[(rowa + 8) * 68 + colloc] = make_float2(d2, d3);
            }
        }
    }
    __syncthreads();
    float vv[2][4][4];
    if (!is3 && act) {
#pragma unroll
        for (int mt = 0; mt < 2; mt++) {
            int rowa = mrow + mt * 16 + (lane >> 2);
            int ta = s_tok[rowa], tb = s_tok[rowa + 8];
            float sxa = (ta >= 0) ? g_xs[ta] : 0.f;
            float sxb = (tb >= 0) ? g_xs[tb] : 0.f;
            float lm0 = 0.f, lm1 = 0.f;
#pragma unroll
            for (int ns = 0; ns < 4; ns++) {
                int colloc = ncol + ns * 8 + 2 * (lane & 3);
                int col = c0 + colloc;
                float sw0 = ws[e * I_DIM + col];
                float sw1 = ws[e * I_DIM + col + 1];
                int* hh = chh[mt][ns]; int* cr = ccr[mt][ns];
                float d0 = sxa * sw0 * fmaf((float)cr[0], 0.0078125f, (float)hh[0]);
                float d1 = sxa * sw1 * fmaf((float)cr[1], 0.0078125f, (float)hh[1]);
                float d2 = sxb * sw0 * fmaf((float)cr[2], 0.0078125f, (float)hh[2]);
                float d3 = sxb * sw1 * fmaf((float)cr[3], 0.0078125f, (float)hh[3]);
                float2 e3a = *(float2*)&stg[rowa * 68 + colloc];
                float2 e3b = *(float2*)&stg[(rowa + 8) * 68 + colloc];
                float v0 = d0 * e3a.x / (1.f + __expf(-d0));
                float v1 = d1 * e3a.y / (1.f + __expf(-d1));
                float v2 = d2 * e3b.x / (1.f + __expf(-d2));
                float v3 = d3 * e3b.y / (1.f + __expf(-d3));
                vv[mt][ns][0] = v0; vv[mt][ns][1] = v1;
                vv[mt][ns][2] = v2; vv[mt][ns][3] = v3;
                lm0 = fmaxf(lm0, fmaxf(fabsf(v0), fabsf(v1)));
                lm1 = fmaxf(lm1, fmaxf(fabsf(v2), fabsf(v3)));
            }
            atomicMax((unsigned int*)&s_amax[rowa],     __float_as_uint(lm0));
            atomicMax((unsigned int*)&s_amax[rowa + 8], __float_as_uint(lm1));
        }
    }
    __syncthreads();
    if (!is3 && act) {
#pragma unroll
        for (int mt = 0; mt < 2; mt++) {
            int rowa = mrow + mt * 16 + (lane >> 2);
            float inva = 127.f / fmaxf(s_amax[rowa],     1e-20f);
            float invb = 127.f / fmaxf(s_amax[rowa + 8], 1e-20f);
#pragma unroll
            for (int ns = 0; ns < 4; ns++) {
                int col = c0 + ncol + ns * 8 + 2 * (lane & 3);
                int q0, l0, q1, l1, q2, l2, q3, l3;
                quant2(vv[mt][ns][0], inva, q0, l0);
                quant2(vv[mt][ns][1], inva, q1, l1);
                quant2(vv[mt][ns][2], invb, q2, l2);
                quant2(vv[mt][ns][3], invb, q3, l3);
                size_t o0 = (size_t)(r0 + rowa) * I_DIM + col;
                size_t o1 = (size_t)(r0 + rowa + 8) * I_DIM + col;
                *(unsigned short*)(g_hqh + o0) = pack2(q0, q1);
                *(unsigned short*)(g_hql + o0) = pack2(l0, l1);
                *(unsigned short*)(g_hqh + o1) = pack2(q2, q3);
                *(unsigned short*)(g_hql + o1) = pack2(l2, l3);
            }
        }
    }
    if (tid < 128)
        g_hs[(size_t)blockIdx.x * NPOS + r0 + tid]
            = fmaxf(s_amax[tid], 1e-20f) * (1.f / 127.f);
}

// ---------------- GEMM2 (int8 two-level): CTA 128x64, 16 warps, m32xn16 ------
__global__ __launch_bounds__(512, 1)
void gemm2_kernel() {
    extern __shared__ __align__(128) char sm[];
    int e = g_tile_expert[blockIdx.y];
    if (e < 0) return;
    int tid = threadIdx.x, lane = tid & 31, wid = tid >> 5;
    int r0 = g_tile_r0[blockIdx.y];
    int rows = g_tile_rows[blockIdx.y];
    int c0 = blockIdx.x * 64;
    uint32_t tiles_u = smem_u32(sm);

    int mrow = (wid >> 2) * 32;
    int ncol = (wid & 3) * 16;
    bool act = (mrow < rows);

    float c[2][2][4];
#pragma unroll
    for (int a = 0; a < 2; a++)
#pragma unroll
        for (int b = 0; b < 2; b++)
#pragma unroll
            for (int q = 0; q < 4; q++) c[a][b][q] = 0.f;

    // per-column w2 scales (constant across K)
    float sbc[2][2];
#pragma unroll
    for (int sub = 0; sub < 2; sub++)
#pragma unroll
        for (int p = 0; p < 2; p++)
            sbc[sub][p] = g_w2s[e * D_DIM + c0 + ncol + sub * 8 + 2 * (lane & 3) + p];

    auto issue_stage = [&](int kc, int st) {
        uint32_t base = tiles_u + st * STAGE2Q;
        int kb = kc * 64;
#pragma unroll
        for (int it = 0; it < 4; it++) {
            int gid = it * 512 + tid;
            if (gid < 1024) {
                int hl = gid >> 9, g = gid & 511;
                int r = g >> 2, cc = g & 3;
                const int8_t* spq = (hl ? g_hql : g_hqh)
                    + ((size_t)(r0 + r) * I_DIM + kb + cc * 16);
                cp16(base + (hl ? H_AL : H_AH) + r * 80 + cc * 16, spq);
            } else if (gid < 1536) {
                int g2 = gid - 1024;
                int hl = g2 >> 8, r = (g2 >> 2) & 63, cc = g2 & 3;
                const int8_t* spq = (hl ? g_w2ql : g_w2qh)
                    + (((size_t)e * D_DIM + c0 + r) * I_DIM + kb + cc * 16);
                cp16(base + (hl ? H_BL : H_BH) + r * 80 + cc * 16, spq);
            } else if (gid < 1568) {
                int r4 = gid - 1536;
                cp16(base + H_AS + r4 * 16,
                     g_hs + (size_t)kc * NPOS + r0 + r4 * 4);
            }
        }
    };

    auto compute = [&](int st) {
        if (!act) return;
        uint32_t su = tiles_u + st * STAGE2Q;
        const float* sc = (const float*)(sm + st * STAGE2Q + H_AS);
        float sa[2][2];
#pragma unroll
        for (int mt = 0; mt < 2; mt++) {
            int ra = mrow + mt * 16 + (lane >> 2);
            sa[mt][0] = sc[ra];
            sa[mt][1] = sc[ra + 8];
        }
        int hh[2][2][4], cr[2][2][4];
#pragma unroll
        for (int a = 0; a < 2; a++)
#pragma unroll
            for (int b = 0; b < 2; b++)
#pragma unroll
                for (int q = 0; q < 4; q++) { hh[a][b][q] = 0; cr[a][b][q] = 0; }
#pragma unroll
        for (int ks = 0; ks < 2; ks++) {
            int ko = ks * 32;
            uint32_t ah[2][4], al[2][4];
#pragma unroll
            for (int mt = 0; mt < 2; mt++) {
                uint32_t aaddr = su + H_AH
                    + (uint32_t)((mrow + mt * 16 + (lane & 15)) * 80 + ko + (lane >> 4) * 16);
                ldm_x4(ah[mt], aaddr);
                ldm_x4(al[mt], aaddr + (H_AL - H_AH));
            }
            uint32_t bh[4], bl[4];
            uint32_t baddr = su + H_BH
                + (uint32_t)((ncol + (lane & 15)) * 80 + ko + (lane >> 4) * 16);
            ldm_x4(bh, baddr);
            ldm_x4(bl, baddr + (H_BL - H_BH));
#pragma unroll
            for (int mt = 0; mt < 2; mt++)
#pragma unroll
                for (int sub = 0; sub < 2; sub++) {
                    mma_s8(hh[mt][sub], ah[mt], bh[sub], bh[sub + 2]);
                    mma_s8(cr[mt][sub], al[mt], bh[sub], bh[sub + 2]);
                    mma_s8(cr[mt][sub], ah[mt], bl[sub], bl[sub + 2]);
                }
        }
        // dequantize this K-chunk into fp32 accumulators
#pragma unroll
        for (int mt = 0; mt < 2; mt++)
#pragma unroll
            for (int sub = 0; sub < 2; sub++)
#pragma unroll
                for (int q = 0; q < 4; q++) {
                    float v = fmaf((float)cr[mt][sub][q], 0.0078125f,
                                   (float)hh[mt][sub][q]);
                    c[mt][sub][q] = fmaf(sa[mt][q >> 1] * sbc[sub][q & 1], v,
                                         c[mt][sub][q]);
                }
    };

    issue_stage(0, 0); cp_commit();
    issue_stage(1, 1); cp_commit();
#pragma unroll 1
    for (int kc = 0; kc < NCHUNK; kc++) {
        if (kc < NCHUNK - 1) cp_wait<1>(); else cp_wait<0>();
        __syncthreads();
        compute(kc & 1);
        __syncthreads();
        if (kc + 2 < NCHUNK) { issue_stage(kc + 2, kc & 1); cp_commit(); }
    }

    if (act) {
#pragma unroll
        for (int mt = 0; mt < 2; mt++) {
            int row = mrow + mt * 16 + (lane >> 2);
            float wa = g_pos_wt[r0 + row];
            float wb = g_pos_wt[r0 + row + 8];
#pragma unroll
            for (int sub = 0; sub < 2; sub++) {
                int col = c0 + ncol + sub * 8 + 2 * (lane & 3);
                float* cc = c[mt][sub];
                *(float2*)(g_y + (size_t)(r0 + row) * D_DIM + col)
                    = make_float2(cc[0] * wa, cc[1] * wa);
                *(float2*)(g_y + (size_t)(r0 + row + 8) * D_DIM + col)
                    = make_float2(cc[2] * wb, cc[3] * wb);
            }
        }
    }
}

// ---------------- combine ----------------------------------------------------
__global__ void combine_kernel(float* __restrict__ out, int T) {
    int idx = blockIdx.x * blockDim.x + threadIdx.x;
    int total = T * (D_DIM / 4);
    if (idx >= total) return;
    int t = idx / (D_DIM / 4);
    int d4 = idx - t * (D_DIM / 4);
    int p0 = g_slot_pos[2 * t];
    int p1 = g_slot_pos[2 * t + 1];
    const float4* y0 = (const float4*)(g_y + (size_t)p0 * D_DIM) + d4;
    const float4* y1 = (const float4*)(g_y + (size_t)p1 * D_DIM) + d4;
    float4 a = *y0, b = *y1;
    float4 r;
    r.x = a.x + b.x; r.y = a.y + b.y; r.z = a.z + b.z; r.w = a.w + b.w;
    ((float4*)out)[idx] = r;
}

// ---------------- launch -----------------------------------------------------
extern "C" void kernel_launch(void* const* d_in, const int* in_sizes, int n_in,
                              void* d_out, int out_size) {
    const float* x  = (const float*)d_in[0];
    const float* gw = (const float*)d_in[1];
    const float* w1 = (const float*)d_in[2];
    const float* w2 = (const float*)d_in[3];
    const float* w3 = (const float*)d_in[4];
    float* out = (float*)d_out;

    int T = in_sizes[0] / D_DIM;
    if (T > T_MAX) T = T_MAX;

    cudaFuncSetAttribute(gemm1_kernel, cudaFuncAttributeMaxDynamicSharedMemorySize, SMEM1);
    cudaFuncSetAttribute(gemm2_kernel, cudaFuncAttributeMaxDynamicSharedMemorySize, SMEM2);

    init_kernel<<<(NPOS + 255) / 256, 256>>>();
    prep_kernel<<<NB_GATE + NB_XQ + NB_WQ + NB_W2, 256>>>(x, gw, w1, w3, w2, T);
    offsets_kernel<<<1, 32>>>();
    scatter_kernel<<<(T * TOPK + 255) / 256, 256>>>(T);

    dim3 grid1(I_DIM / 64, NTILE);
    gemm1_kernel<<<grid1, 512, SMEM1>>>();

    dim3 grid2(D_DIM / 64, NTILE);
    gemm2_kernel<<<grid2, 512, SMEM2>>>();

    combine_kernel<<<(T * (D_DIM / 4) + 255) / 256, 256>>>(out, T);
}

// round 17
// speedup vs baseline: 1.3915x; 1.0131x over previous
#include <cuda_runtime.h>
#include <cuda_bf16.h>
#include <cstdint>
#include <math.h>

#define D_DIM 1024
#define I_DIM 4096
#define E_NUM 8
#define TOPK  2
#define T_MAX 2048
#define PADG  64
#define NPOS  (T_MAX*TOPK + E_NUM*128)    // 5120 upper bound
#define NTILE 44
#define NCHUNK (I_DIM/64)                 // 64 K-chunks of h

// ---- GEMM1 stage (int8): A Qh/Ql 128r + B1 Qh/Ql 64r + B3 Qh/Ql 64r, 80B pitch
#define STAGE1 40960
#define Q_AH   0
#define Q_AL   10240
#define Q_B1H  20480
#define Q_B1L  25600
#define Q_B3H  30720
#define Q_B3L  35840
#define SMEM1  (512 + 3*STAGE1)           // 123392

// ---- GEMM2 stage (int8): A(h) Qh/Ql 128r + B(w2) Qh/Ql 128r + A-scales -----
#define STAGE2Q 41472
#define H_AH   0
#define H_AL   10240
#define H_BH   20480
#define H_BL   30720
#define H_AS   40960                      // 128 fp32 per-row chunk scales
#define SMEM2  (3*STAGE2Q)                // 124416

// ---------------- scratch ----------------------------------------------------
__device__ int   g_counts[E_NUM];
__device__ int   g_offsets[E_NUM + 1];
__device__ int   g_cursor[E_NUM];
__device__ int   g_tile_expert[NTILE];
__device__ int   g_tile_r0[NTILE];
__device__ int   g_tile_rows[NTILE];
__device__ int   g_pos_token[NPOS];
__device__ float g_pos_wt[NPOS];
__device__ int   g_slot_pos[T_MAX * TOPK];
__device__ int   g_tok_eidx[T_MAX * TOPK];
__device__ float g_tok_ewt[T_MAX * TOPK];

__device__ int8_t g_xqh[(size_t)T_MAX * D_DIM];
__device__ int8_t g_xql[(size_t)T_MAX * D_DIM];
__device__ float  g_xs[T_MAX];
__device__ int8_t g_w1qh[(size_t)E_NUM * I_DIM * D_DIM];
__device__ int8_t g_w1ql[(size_t)E_NUM * I_DIM * D_DIM];
__device__ int8_t g_w3qh[(size_t)E_NUM * I_DIM * D_DIM];
__device__ int8_t g_w3ql[(size_t)E_NUM * I_DIM * D_DIM];
__device__ float  g_w1s[E_NUM * I_DIM];
__device__ float  g_w3s[E_NUM * I_DIM];

__device__ int8_t g_w2qh[(size_t)E_NUM * D_DIM * I_DIM];
__device__ int8_t g_w2ql[(size_t)E_NUM * D_DIM * I_DIM];
__device__ float  g_w2s[E_NUM * D_DIM];
__device__ int8_t g_hqh[(size_t)NPOS * I_DIM];
__device__ int8_t g_hql[(size_t)NPOS * I_DIM];
__device__ float  g_hs[(size_t)NCHUNK * NPOS];   // [chunk][pos]
__device__ float  g_y[(size_t)NPOS * D_DIM];

// ---------------- helpers ----------------------------------------------------
__device__ __forceinline__ uint32_t smem_u32(const void* p) {
    uint32_t a;
    asm("{ .reg .u64 t; cvta.to.shared.u64 t, %1; cvt.u32.u64 %0, t; }" : "=r"(a) : "l"(p));
    return a;
}
__device__ __forceinline__ void ldm_x4(uint32_t* r, uint32_t addr) {
    asm volatile("ldmatrix.sync.aligned.m8n8.x4.shared.b16 {%0,%1,%2,%3}, [%4];"
        : "=r"(r[0]), "=r"(r[1]), "=r"(r[2]), "=r"(r[3]) : "r"(addr));
}
__device__ __forceinline__ void mma_s8(int* c, const uint32_t* a, uint32_t b0, uint32_t b1) {
    asm volatile("mma.sync.aligned.m16n8k32.row.col.s32.s8.s8.s32 "
        "{%0,%1,%2,%3}, {%4,%5,%6,%7}, {%8,%9}, {%0,%1,%2,%3};"
        : "+r"(c[0]), "+r"(c[1]), "+r"(c[2]), "+r"(c[3])
        : "r"(a[0]), "r"(a[1]), "r"(a[2]), "r"(a[3]), "r"(b0), "r"(b1));
}
__device__ __forceinline__ void cp16(uint32_t dst, const void* src) {
    asm volatile("cp.async.cg.shared.global [%0], [%1], 16;" :: "r"(dst), "l"(src) : "memory");
}
__device__ __forceinline__ void cp16z(uint32_t dst, const void* src, int nbytes) {
    asm volatile("cp.async.cg.shared.global [%0], [%1], 16, %2;"
        :: "r"(dst), "l"(src), "r"(nbytes) : "memory");
}
__device__ __forceinline__ void cp_commit() {
    asm volatile("cp.async.commit_group;" ::: "memory");
}
template <int N>
__device__ __forceinline__ void cp_wait() {
    asm volatile("cp.async.wait_group %0;" :: "n"(N) : "memory");
}
__device__ __forceinline__ void quant2(float v, float inv, int& q, int& ql) {
    float t = v * inv;
    float qf = fminf(fmaxf(rintf(t), -127.f), 127.f);
    q = (int)qf;
    ql = (int)fminf(fmaxf(rintf((t - qf) * 128.f), -127.f), 127.f);
}
__device__ __forceinline__ unsigned short pack2(int a, int b) {
    return (unsigned short)((a & 0xFF) | ((b & 0xFF) << 8));
}

// ---------------- init -------------------------------------------------------
__global__ void init_kernel() {
    int i = blockIdx.x * blockDim.x + threadIdx.x;
    if (i < E_NUM) g_counts[i] = 0;
    if (i < NPOS) { g_pos_token[i] = -1; g_pos_wt[i] = 0.f; }
}

// ---------------- fused prep: gate + quant x/w1/w3 (1024-rows) + quant w2 ----
#define NB_GATE 256
#define NB_XQ   2048
#define NB_WQ   65536
#define NB_W2   8192
__global__ void prep_kernel(const float* __restrict__ x,
                            const float* __restrict__ gw,
                            const float* __restrict__ w1,
                            const float* __restrict__ w3,
                            const float* __restrict__ w2,
                            int T) {
    __shared__ float red[8];
    int b = blockIdx.x;
    int tid = threadIdx.x;
    if (b < NB_GATE) {
        int gtid = b * 256 + tid;
        int warp = gtid >> 5, lane = gtid & 31;
        if (warp >= T) return;
        const float* xr = x + (size_t)warp * D_DIM;
        float acc[E_NUM];
#pragma unroll
        for (int e = 0; e < E_NUM; e++) acc[e] = 0.f;
        for (int k = lane; k < D_DIM; k += 32) {
            float xv = xr[k];
#pragma unroll
            for (int e = 0; e < E_NUM; e++)
                acc[e] = fmaf(xv, gw[e * D_DIM + k], acc[e]);
        }
#pragma unroll
        for (int e = 0; e < E_NUM; e++)
#pragma unroll
            for (int off = 16; off > 0; off >>= 1)
                acc[e] += __shfl_down_sync(0xFFFFFFFFu, acc[e], off);
        if (lane == 0) {
            int i0 = 0;
#pragma unroll
            for (int e = 1; e < E_NUM; e++) if (acc[e] > acc[i0]) i0 = e;
            int i1 = (i0 == 0) ? 1 : 0;
#pragma unroll
            for (int e = 0; e < E_NUM; e++)
                if (e != i0 && acc[e] > acc[i1]) i1 = e;
            float m = fmaxf(acc[i0], acc[i1]);
            float p0 = __expf(acc[i0] - m), p1 = __expf(acc[i1] - m);
            float s = p0 + p1;
            int base = warp * TOPK;
            g_tok_eidx[base + 0] = i0; g_tok_ewt[base + 0] = p0 / s;
            g_tok_eidx[base + 1] = i1; g_tok_ewt[base + 1] = p1 / s;
            atomicAdd(&g_counts[i0], 1);
            atomicAdd(&g_counts[i1], 1);
        }
    } else if (b < NB_GATE + NB_XQ + NB_WQ) {
        const float* src; int8_t* qh; int8_t* ql; float* sp;
        if (b < NB_GATE + NB_XQ) {
            int t = b - NB_GATE;
            if (t >= T) return;
            src = x + (size_t)t * D_DIM;
            qh = g_xqh + (size_t)t * D_DIM;
            ql = g_xql + (size_t)t * D_DIM;
            sp = g_xs + t;
        } else {
            int idx = b - NB_GATE - NB_XQ;
            int mat = idx >> 15;
            int row = idx & 32767;
            src = (mat ? w3 : w1) + (size_t)row * D_DIM;
            qh = (mat ? g_w3qh : g_w1qh) + (size_t)row * D_DIM;
            ql = (mat ? g_w3ql : g_w1ql) + (size_t)row * D_DIM;
            sp = (mat ? g_w3s : g_w1s) + row;
        }
        float4 v = ((const float4*)src)[tid];
        float am = fmaxf(fmaxf(fabsf(v.x), fabsf(v.y)), fmaxf(fabsf(v.z), fabsf(v.w)));
#pragma unroll
        for (int off = 16; off > 0; off >>= 1)
            am = fmaxf(am, __shfl_xor_sync(0xFFFFFFFFu, am, off));
        if ((tid & 31) == 0) red[tid >> 5] = am;
        __syncthreads();
        float m2 = red[0];
#pragma unroll
        for (int j = 1; j < 8; j++) m2 = fmaxf(m2, red[j]);
        float s = fmaxf(m2, 1e-20f) * (1.f / 127.f);
        float inv = 1.f / s;
        int q0, l0, q1, l1, q2, l2, q3, l3;
        quant2(v.x, inv, q0, l0); quant2(v.y, inv, q1, l1);
        quant2(v.z, inv, q2, l2); quant2(v.w, inv, q3, l3);
        ((char4*)qh)[tid] = make_char4(q0, q1, q2, q3);
        ((char4*)ql)[tid] = make_char4(l0, l1, l2, l3);
        if (tid == 0) *sp = s;
    } else {
        int row = b - NB_GATE - NB_XQ - NB_WQ;
        const float* src = w2 + (size_t)row * I_DIM;
        float4 v[4];
        float am = 0.f;
#pragma unroll
        for (int i = 0; i < 4; i++) {
            v[i] = ((const float4*)src)[tid + i * 256];
            am = fmaxf(am, fmaxf(fmaxf(fabsf(v[i].x), fabsf(v[i].y)),
                                 fmaxf(fabsf(v[i].z), fabsf(v[i].w))));
        }
#pragma unroll
        for (int off = 16; off > 0; off >>= 1)
            am = fmaxf(am, __shfl_xor_sync(0xFFFFFFFFu, am, off));
        if ((tid & 31) == 0) red[tid >> 5] = am;
        __syncthreads();
        float m2 = red[0];
#pragma unroll
        for (int j = 1; j < 8; j++) m2 = fmaxf(m2, red[j]);
        float s = fmaxf(m2, 1e-20f) * (1.f / 127.f);
        float inv = 1.f / s;
#pragma unroll
        for (int i = 0; i < 4; i++) {
            int q0, l0, q1, l1, q2, l2, q3, l3;
            quant2(v[i].x, inv, q0, l0); quant2(v[i].y, inv, q1, l1);
            quant2(v[i].z, inv, q2, l2); quant2(v[i].w, inv, q3, l3);
            ((char4*)(g_w2qh + (size_t)row * I_DIM))[tid + i * 256]
                = make_char4(q0, q1, q2, q3);
            ((char4*)(g_w2ql + (size_t)row * I_DIM))[tid + i * 256]
                = make_char4(l0, l1, l2, l3);
        }
        if (tid == 0) g_w2s[row] = s;
    }
}

// ---------------- offsets + tile table ---------------------------------------
__global__ void offsets_kernel() {
    if (threadIdx.x == 0 && blockIdx.x == 0) {
        int total = 0;
        for (int e = 0; e < E_NUM; e++) {
            g_offsets[e] = total;
            g_cursor[e]  = total;
            total += (g_counts[e] + PADG - 1) & ~(PADG - 1);
        }
        g_offsets[E_NUM] = total;
        int nt = 0;
        for (int e = 0; e < E_NUM; e++) {
            int sz = g_offsets[e + 1] - g_offsets[e];
            int r = 0;
            while (r < sz && nt < NTILE) {
                g_tile_expert[nt] = e;
                g_tile_r0[nt]     = g_offsets[e] + r;
                g_tile_rows[nt]   = (sz - r >= 128) ? 128 : 64;
                r += 128;
                nt++;
            }
        }
        for (int t = nt; t < NTILE; t++) g_tile_expert[t] = -1;
    }
}

__global__ void scatter_kernel(int T) {
    int idx = blockIdx.x * blockDim.x + threadIdx.x;
    if (idx >= T * TOPK) return;
    int e = g_tok_eidx[idx];
    int pos = atomicAdd(&g_cursor[e], 1);
    g_pos_token[pos] = idx >> 1;
    g_pos_wt[pos]    = g_tok_ewt[idx];
    g_slot_pos[idx]  = pos;
}

// ---------------- GEMM1 (int8 two-level): CTA 128x64, 16 warps, 3-stage ------
__global__ __launch_bounds__(512, 1)
void gemm1_kernel() {
    extern __shared__ __align__(128) char sm[];
    int e = g_tile_expert[blockIdx.y];
    if (e < 0) return;
    int tid = threadIdx.x, lane = tid & 31, wid = tid >> 5;
    int r0 = g_tile_r0[blockIdx.y];
    int rows = g_tile_rows[blockIdx.y];
    int c0 = blockIdx.x * 64;
    int* s_tok = (int*)sm;
    uint32_t tiles_u = smem_u32(sm) + 512;

    if (tid < 128) s_tok[tid] = (tid < rows) ? g_pos_token[r0 + tid] : -1;
    __syncthreads();

    int is3 = wid >> 3;
    int wl = wid & 7;
    int mrow = (wl >> 1) * 32;
    int ncol = (wl & 1) * 32;
    bool act = (mrow < rows);

    int chh[2][4][4], ccr[2][4][4];
#pragma unroll
    for (int a = 0; a < 2; a++)
#pragma unroll
        for (int b = 0; b < 4; b++)
#pragma unroll
            for (int q = 0; q < 4; q++) { chh[a][b][q] = 0; ccr[a][b][q] = 0; }

    auto issue_stage = [&](int kc, int st) {
        uint32_t base = tiles_u + st * STAGE1;
        int kb = kc * 64;
#pragma unroll
        for (int it = 0; it < 4; it++) {
            int gid = it * 512 + tid;
            if (gid < 1024) {
                int hl = gid >> 9, g = gid & 511;
                int r = g >> 2, cc = g & 3;
                int tok = s_tok[r];
                const int8_t* spq = (hl ? g_xql : g_xqh)
                    + ((size_t)(tok >= 0 ? tok : 0) * D_DIM + kb + cc * 16);
                cp16z(base + (hl ? Q_AL : Q_AH) + r * 80 + cc * 16, spq,
                      tok >= 0 ? 16 : 0);
            } else {
                int g2 = gid - 1024;
                int mat = g2 >> 9, g3 = g2 & 511;
                int hl = g3 >> 8, r = (g3 >> 2) & 63, cc = g3 & 3;
                const int8_t* wq = mat ? (hl ? g_w3ql : g_w3qh)
                                       : (hl ? g_w1ql : g_w1qh);
                const int8_t* spq = wq
                    + (((size_t)e * I_DIM + c0 + r) * D_DIM + kb + cc * 16);
                uint32_t off = (mat ? Q_B3H : Q_B1H) + (hl ? 5120u : 0u)
                             + r * 80 + cc * 16;
                cp16(base + off, spq);
            }
        }
    };

    auto compute = [&](int st) {
        if (!act) return;
        uint32_t su = tiles_u + st * STAGE1;
        uint32_t bb = su + (is3 ? Q_B3H : Q_B1H);
#pragma unroll
        for (int ks = 0; ks < 2; ks++) {
            int ko = ks * 32;
            uint32_t ah[2][4], al[2][4];
#pragma unroll
            for (int mt = 0; mt < 2; mt++) {
                uint32_t aaddr = su + Q_AH
                    + (uint32_t)((mrow + mt * 16 + (lane & 15)) * 80 + ko + (lane >> 4) * 16);
                ldm_x4(ah[mt], aaddr);
                ldm_x4(al[mt], aaddr + (Q_AL - Q_AH));
            }
#pragma unroll
            for (int nt = 0; nt < 2; nt++) {
                uint32_t bh[4], bl[4];
                uint32_t baddr = bb
                    + (uint32_t)((ncol + nt * 16 + (lane & 15)) * 80 + ko + (lane >> 4) * 16);
                ldm_x4(bh, baddr);
                ldm_x4(bl, baddr + 5120);
#pragma unroll
                for (int mt = 0; mt < 2; mt++)
#pragma unroll
                    for (int sub = 0; sub < 2; sub++) {
                        int* cc1 = chh[mt][nt * 2 + sub];
                        int* cc2 = ccr[mt][nt * 2 + sub];
                        mma_s8(cc1, ah[mt], bh[sub], bh[sub + 2]);
                        mma_s8(cc2, al[mt], bh[sub], bh[sub + 2]);
                        mma_s8(cc2, ah[mt], bl[sub], bl[sub + 2]);
                    }
            }
        }
    };

    issue_stage(0, 0); cp_commit();
    issue_stage(1, 1); cp_commit();
#pragma unroll 1
    for (int kc = 0; kc < 16; kc++) {
        if (kc < 15) cp_wait<1>(); else cp_wait<0>();
        __syncthreads();
        if (kc + 2 < 16) { issue_stage(kc + 2, (kc + 2) % 3); cp_commit(); }
        compute(kc % 3);
    }
    __syncthreads();   // all computes done before smem reuse by epilogue

    // epilogue: d3 exchange, silu, per-(row,chunk) two-level int8 quant of h
    float* stg    = (float*)(sm + 512);            // [128][68] d3 exchange
    float* s_amax = (float*)(sm + 512 + 34816);    // 128 row absmax
    if (tid < 128) s_amax[tid] = 0.f;
    const float* ws = is3 ? g_w3s : g_w1s;
    if (is3 && act) {
#pragma unroll
        for (int mt = 0; mt < 2; mt++) {
            int rowa = mrow + mt * 16 + (lane >> 2);
            int ta = s_tok[rowa], tb = s_tok[rowa + 8];
            float sxa = (ta >= 0) ? g_xs[ta] : 0.f;
            float sxb = (tb >= 0) ? g_xs[tb] : 0.f;
#pragma unroll
            for (int ns = 0; ns < 4; ns++) {
                int colloc = ncol + ns * 8 + 2 * (lane & 3);
                int col = c0 + colloc;
                float sw0 = ws[e * I_DIM + col];
                float sw1 = ws[e * I_DIM + col + 1];
                int* hh = chh[mt][ns]; int* cr = ccr[mt][ns];
                float d0 = sxa * sw0 * fmaf((float)cr[0], 0.0078125f, (float)hh[0]);
                float d1 = sxa * sw1 * fmaf((float)cr[1], 0.0078125f, (float)hh[1]);
                float d2 = sxb * sw0 * fmaf((float)cr[2], 0.0078125f, (float)hh[2]);
                float d3 = sxb * sw1 * fmaf((float)cr[3], 0.0078125f, (float)hh[3]);
                *(float2*)&stg[rowa * 68 + colloc]       = make_float2(d0, d1);
                *(float2*)&stg[(rowa + 8) * 68 + colloc] = make_float2(d2, d3);
            }
        }
    }
    __syncthreads();
    float vv[2][4][4];
    if (!is3 && act) {
#pragma unroll
        for (int mt = 0; mt < 2; mt++) {
            int rowa = mrow + mt * 16 + (lane >> 2);
            int ta = s_tok[rowa], tb = s_tok[rowa + 8];
            float sxa = (ta >= 0) ? g_xs[ta] : 0.f;
            float sxb = (tb >= 0) ? g_xs[tb] : 0.f;
            float lm0 = 0.f, lm1 = 0.f;
#pragma unroll
            for (int ns = 0; ns < 4; ns++) {
                int colloc = ncol + ns * 8 + 2 * (lane & 3);
                int col = c0 + colloc;
                float sw0 = ws[e * I_DIM + col];
                float sw1 = ws[e * I_DIM + col + 1];
                int* hh = chh[mt][ns]; int* cr = ccr[mt][ns];
                float d0 = sxa * sw0 * fmaf((float)cr[0], 0.0078125f, (float)hh[0]);
                float d1 = sxa * sw1 * fmaf((float)cr[1], 0.0078125f, (float)hh[1]);
                float d2 = sxb * sw0 * fmaf((float)cr[2], 0.0078125f, (float)hh[2]);
                float d3 = sxb * sw1 * fmaf((float)cr[3], 0.0078125f, (float)hh[3]);
                float2 e3a = *(float2*)&stg[rowa * 68 + colloc];
                float2 e3b = *(float2*)&stg[(rowa + 8) * 68 + colloc];
                float v0 = d0 * e3a.x / (1.f + __expf(-d0));
                float v1 = d1 * e3a.y / (1.f + __expf(-d1));
                float v2 = d2 * e3b.x / (1.f + __expf(-d2));
                float v3 = d3 * e3b.y / (1.f + __expf(-d3));
                vv[mt][ns][0] = v0; vv[mt][ns][1] = v1;
                vv[mt][ns][2] = v2; vv[mt][ns][3] = v3;
                lm0 = fmaxf(lm0, fmaxf(fabsf(v0), fabsf(v1)));
                lm1 = fmaxf(lm1, fmaxf(fabsf(v2), fabsf(v3)));
            }
            atomicMax((unsigned int*)&s_amax[rowa],     __float_as_uint(lm0));
            atomicMax((unsigned int*)&s_amax[rowa + 8], __float_as_uint(lm1));
        }
    }
    __syncthreads();
    if (!is3 && act) {
#pragma unroll
        for (int mt = 0; mt < 2; mt++) {
            int rowa = mrow + mt * 16 + (lane >> 2);
            float inva = 127.f / fmaxf(s_amax[rowa],     1e-20f);
            float invb = 127.f / fmaxf(s_amax[rowa + 8], 1e-20f);
#pragma unroll
            for (int ns = 0; ns < 4; ns++) {
                int col = c0 + ncol + ns * 8 + 2 * (lane & 3);
                int q0, l0, q1, l1, q2, l2, q3, l3;
                quant2(vv[mt][ns][0], inva, q0, l0);
                quant2(vv[mt][ns][1], inva, q1, l1);
                quant2(vv[mt][ns][2], invb, q2, l2);
                quant2(vv[mt][ns][3], invb, q3, l3);
                size_t o0 = (size_t)(r0 + rowa) * I_DIM + col;
                size_t o1 = (size_t)(r0 + rowa + 8) * I_DIM + col;
                *(unsigned short*)(g_hqh + o0) = pack2(q0, q1);
                *(unsigned short*)(g_hql + o0) = pack2(l0, l1);
                *(unsigned short*)(g_hqh + o1) = pack2(q2, q3);
                *(unsigned short*)(g_hql + o1) = pack2(l2, l3);
            }
        }
    }
    if (tid < 128)
        g_hs[(size_t)blockIdx.x * NPOS + r0 + tid]
            = fmaxf(s_amax[tid], 1e-20f) * (1.f / 127.f);
}

// ---------------- GEMM2 (int8 two-level): CTA 128x128, 16 warps, m32xn32 -----
__global__ __launch_bounds__(512, 1)
void gemm2_kernel() {
    extern __shared__ __align__(128) char sm[];
    int e = g_tile_expert[blockIdx.y];
    if (e < 0) return;
    int tid = threadIdx.x, lane = tid & 31, wid = tid >> 5;
    int r0 = g_tile_r0[blockIdx.y];
    int rows = g_tile_rows[blockIdx.y];
    int c0 = blockIdx.x * 128;
    uint32_t tiles_u = smem_u32(sm);

    int mrow = (wid >> 2) * 32;
    int ncol = (wid & 3) * 32;
    bool act = (mrow < rows);

    float c[2][4][4];
#pragma unroll
    for (int a = 0; a < 2; a++)
#pragma unroll
        for (int b = 0; b < 4; b++)
#pragma unroll
            for (int q = 0; q < 4; q++) c[a][b][q] = 0.f;

    // per-column w2 scales (constant across K)
    float sbc[4][2];
#pragma unroll
    for (int sub = 0; sub < 4; sub++)
#pragma unroll
        for (int p = 0; p < 2; p++)
            sbc[sub][p] = g_w2s[e * D_DIM + c0 + ncol + sub * 8 + 2 * (lane & 3) + p];

    auto issue_stage = [&](int kc, int st) {
        uint32_t base = tiles_u + st * STAGE2Q;
        int kb = kc * 64;
#pragma unroll
        for (int it = 0; it < 4; it++) {
            int gid = it * 512 + tid;
            if (gid < 1024) {
                int hl = gid >> 9, g = gid & 511;
                int r = g >> 2, cc = g & 3;
                const int8_t* spq = (hl ? g_hql : g_hqh)
                    + ((size_t)(r0 + r) * I_DIM + kb + cc * 16);
                cp16(base + (hl ? H_AL : H_AH) + r * 80 + cc * 16, spq);
            } else {
                int g2 = gid - 1024;
                int hl = g2 >> 9, g3 = g2 & 511;
                int r = g3 >> 2, cc = g3 & 3;
                const int8_t* spq = (hl ? g_w2ql : g_w2qh)
                    + (((size_t)e * D_DIM + c0 + r) * I_DIM + kb + cc * 16);
                cp16(base + (hl ? H_BL : H_BH) + r * 80 + cc * 16, spq);
            }
        }
        if (tid < 32)
            cp16(base + H_AS + tid * 16,
                 g_hs + (size_t)kc * NPOS + r0 + tid * 4);
    };

    auto compute = [&](int st) {
        if (!act) return;
        uint32_t su = tiles_u + st * STAGE2Q;
        const float* sc = (const float*)(sm + st * STAGE2Q + H_AS);
        float sa[2][2];
#pragma unroll
        for (int mt = 0; mt < 2; mt++) {
            int ra = mrow + mt * 16 + (lane >> 2);
            sa[mt][0] = sc[ra];
            sa[mt][1] = sc[ra + 8];
        }
#pragma unroll
        for (int ks = 0; ks < 2; ks++) {
            int ko = ks * 32;
            uint32_t ah[2][4], al[2][4];
#pragma unroll
            for (int mt = 0; mt < 2; mt++) {
                uint32_t aaddr = su + H_AH
                    + (uint32_t)((mrow + mt * 16 + (lane & 15)) * 80 + ko + (lane >> 4) * 16);
                ldm_x4(ah[mt], aaddr);
                ldm_x4(al[mt], aaddr + (H_AL - H_AH));
            }
#pragma unroll
            for (int nt = 0; nt < 2; nt++) {     // two n16 subtiles of n32
                uint32_t bh[4], bl[4];
                uint32_t baddr = su + H_BH
                    + (uint32_t)((ncol + nt * 16 + (lane & 15)) * 80 + ko + (lane >> 4) * 16);
                ldm_x4(bh, baddr);
                ldm_x4(bl, baddr + (H_BL - H_BH));
                int hh[2][2][4], cr[2][2][4];
#pragma unroll
                for (int a = 0; a < 2; a++)
#pragma unroll
                    for (int b2 = 0; b2 < 2; b2++)
#pragma unroll
                        for (int q = 0; q < 4; q++) { hh[a][b2][q] = 0; cr[a][b2][q] = 0; }
#pragma unroll
                for (int mt = 0; mt < 2; mt++)
#pragma unroll
                    for (int sub = 0; sub < 2; sub++) {
                        mma_s8(hh[mt][sub], ah[mt], bh[sub], bh[sub + 2]);
                        mma_s8(cr[mt][sub], al[mt], bh[sub], bh[sub + 2]);
                        mma_s8(cr[mt][sub], ah[mt], bl[sub], bl[sub + 2]);
                    }
                // dequantize this k32 step into fp32 accumulators
#pragma unroll
                for (int mt = 0; mt < 2; mt++)
#pragma unroll
                    for (int sub = 0; sub < 2; sub++)
#pragma unroll
                        for (int q = 0; q < 4; q++) {
                            float v = fmaf((float)cr[mt][sub][q], 0.0078125f,
                                           (float)hh[mt][sub][q]);
                            c[mt][nt * 2 + sub][q]
                                = fmaf(sa[mt][q >> 1] * sbc[nt * 2 + sub][q & 1],
                                       v, c[mt][nt * 2 + sub][q]);
                        }
            }
        }
    };

    issue_stage(0, 0); cp_commit();
    issue_stage(1, 1); cp_commit();
#pragma unroll 1
    for (int kc = 0; kc < NCHUNK; kc++) {
        if (kc < NCHUNK - 1) cp_wait<1>(); else cp_wait<0>();
        __syncthreads();
        if (kc + 2 < NCHUNK) { issue_stage(kc + 2, (kc + 2) % 3); cp_commit(); }
        compute(kc % 3);
    }

    if (act) {
#pragma unroll
        for (int mt = 0; mt < 2; mt++) {
            int row = mrow + mt * 16 + (lane >> 2);
            float wa = g_pos_wt[r0 + row];
            float wb = g_pos_wt[r0 + row + 8];
#pragma unroll
            for (int sub = 0; sub < 4; sub++) {
                int col = c0 + ncol + sub * 8 + 2 * (lane & 3);
                float* cc = c[mt][sub];
                *(float2*)(g_y + (size_t)(r0 + row) * D_DIM + col)
                    = make_float2(cc[0] * wa, cc[1] * wa);
                *(float2*)(g_y + (size_t)(r0 + row + 8) * D_DIM + col)
                    = make_float2(cc[2] * wb, cc[3] * wb);
            }
        }
    }
}

// ---------------- combine ----------------------------------------------------
__global__ void combine_kernel(float* __restrict__ out, int T) {
    int idx = blockIdx.x * blockDim.x + threadIdx.x;
    int total = T * (D_DIM / 4);
    if (idx >= total) return;
    int t = idx / (D_DIM / 4);
    int d4 = idx - t * (D_DIM / 4);
    int p0 = g_slot_pos[2 * t];
    int p1 = g_slot_pos[2 * t + 1];
    const float4* y0 = (const float4*)(g_y + (size_t)p0 * D_DIM) + d4;
    const float4* y1 = (const float4*)(g_y + (size_t)p1 * D_DIM) + d4;
    float4 a = *y0, b = *y1;
    float4 r;
    r.x = a.x + b.x; r.y = a.y + b.y; r.z = a.z + b.z; r.w = a.w + b.w;
    ((float4*)out)[idx] = r;
}

// ---------------- launch -----------------------------------------------------
extern "C" void kernel_launch(void* const* d_in, const int* in_sizes, int n_in,
                              void* d_out, int out_size) {
    const float* x  = (const float*)d_in[0];
    const float* gw = (const float*)d_in[1];
    const float* w1 = (const float*)d_in[2];
    const float* w2 = (const float*)d_in[3];
    const float* w3 = (const float*)d_in[4];
    float* out = (float*)d_out;

    int T = in_sizes[0] / D_DIM;
    if (T > T_MAX) T = T_MAX;

    cudaFuncSetAttribute(gemm1_kernel, cudaFuncAttributeMaxDynamicSharedMemorySize, SMEM1);
    cudaFuncSetAttribute(gemm2_kernel, cudaFuncAttributeMaxDynamicSharedMemorySize, SMEM2);

    init_kernel<<<(NPOS + 255) / 256, 256>>>();
    prep_kernel<<<NB_GATE + NB_XQ + NB_WQ + NB_W2, 256>>>(x, gw, w1, w3, w2, T);
    offsets_kernel<<<1, 32>>>();
    scatter_kernel<<<(T * TOPK + 255) / 256, 256>>>(T);

    dim3 grid1(I_DIM / 64, NTILE);
    gemm1_kernel<<<grid1, 512, SMEM1>>>();

    dim3 grid2(D_DIM / 128, NTILE);
    gemm2_kernel<<<grid2, 512, SMEM2>>>();

    combine_kernel<<<(T * (D_DIM / 4) + 255) / 256, 256>>>(out, T);
}